// round 6
// baseline (speedup 1.0000x reference)
#include <cuda_runtime.h>
#include <math.h>

#define B_  4
#define S_  1024
#define D_  768
#define H_  12
#define HD_ 64
#define F_  3072
#define L_  12
#define V_  50257
#define T_  (B_*S_)   // 4096 tokens

// ---------------- scratch (device globals; no allocation allowed) ------------
__device__ float g_x[T_*D_];
__device__ float g_h[T_*D_];
__device__ float g_qkv[T_*3*D_];
__device__ float g_attn[T_*D_];
__device__ float g_ff[(size_t)T_*F_];
__device__ float g_scores[(size_t)B_*H_*S_*S_];   // 192 MB

// ---------------- helpers ----------------------------------------------------
__device__ __forceinline__ float gelu_f(float x) {
    float x3 = x * x * x;
    float t = tanhf(0.7978845608028654f * (x + 0.044715f * x3));
    return 0.5f * x * (1.0f + t);
}

// ---------------- embedding --------------------------------------------------
__global__ void __launch_bounds__(256) embed_kernel(
    const int* __restrict__ ids, const float* __restrict__ tok,
    const float* __restrict__ pos, float* __restrict__ x)
{
    int i = blockIdx.x * 256 + threadIdx.x;        // grid exactly covers T_*D_
    int d = i % D_;
    int t = i / D_;
    int s = t & (S_ - 1);
    x[i] = tok[(size_t)ids[t] * D_ + d] + pos[(size_t)s * D_ + d];
}

// ---------------- layernorm (one block per row, 768 = 3*256) -----------------
__global__ void __launch_bounds__(256) ln_kernel(
    const float* __restrict__ x, const float* __restrict__ g,
    const float* __restrict__ b, float* __restrict__ out)
{
    int row = blockIdx.x;
    int tid = threadIdx.x;
    const float* xr = x + (size_t)row * D_;
    float* orow = out + (size_t)row * D_;

    float v0 = xr[tid], v1 = xr[tid + 256], v2 = xr[tid + 512];

    __shared__ float red[8];
    __shared__ float s_stat;

    float s = v0 + v1 + v2;
    #pragma unroll
    for (int o = 16; o; o >>= 1) s += __shfl_xor_sync(0xffffffffu, s, o);
    if ((tid & 31) == 0) red[tid >> 5] = s;
    __syncthreads();
    if (tid == 0) {
        float t = 0.f;
        #pragma unroll
        for (int i = 0; i < 8; i++) t += red[i];
        s_stat = t * (1.0f / D_);
    }
    __syncthreads();
    float mean = s_stat;
    __syncthreads();

    float d0 = v0 - mean, d1 = v1 - mean, d2 = v2 - mean;
    float s2 = d0 * d0 + d1 * d1 + d2 * d2;
    #pragma unroll
    for (int o = 16; o; o >>= 1) s2 += __shfl_xor_sync(0xffffffffu, s2, o);
    if ((tid & 31) == 0) red[tid >> 5] = s2;
    __syncthreads();
    if (tid == 0) {
        float t = 0.f;
        #pragma unroll
        for (int i = 0; i < 8; i++) t += red[i];
        s_stat = rsqrtf(t * (1.0f / D_) + 1e-5f);
    }
    __syncthreads();
    float inv = s_stat;

    orow[tid]       = g[tid]       * (d0 * inv) + b[tid];
    orow[tid + 256] = g[tid + 256] * (d1 * inv) + b[tid + 256];
    orow[tid + 512] = g[tid + 512] * (d2 * inv) + b[tid + 512];
}

// ---------------- SGEMM C = A@B (+bias, +res, +gelu) -------------------------
// 128x128 tile, BK=8, 256 threads, 8x8 per thread.
// EPI: 0 = bias, 1 = bias + residual add, 2 = bias + gelu
template<int EPI>
__global__ void __launch_bounds__(256) gemm_nn(
    const float* __restrict__ A, const float* __restrict__ B,
    const float* __restrict__ bias, const float* __restrict__ res,
    float* __restrict__ C, int M, int N, int K)
{
    __shared__ float As[8][132];   // pad 132 -> conflict-free transposed stores
    __shared__ float Bs[8][128];

    int tid = threadIdx.x;
    int m0 = blockIdx.y * 128;
    int n0 = blockIdx.x * 128;

    int aRow = tid >> 1;
    int aK   = (tid & 1) << 2;
    int bK   = tid >> 5;
    int bN   = (tid & 31) << 2;

    int warp = tid >> 5, lane = tid & 31;
    int tm = ((warp >> 1) << 5) + ((lane >> 3) << 3);          // 0..127 step 8
    int tn = ((warp & 1) << 6) + ((lane & 7) << 2);            // + {0..3, 32..35}

    const float* Ap = A + (size_t)(m0 + aRow) * K + aK;
    const float* Bp = B + (size_t)bK * N + n0 + bN;

    float acc[8][8];
    #pragma unroll
    for (int i = 0; i < 8; i++)
        #pragma unroll
        for (int j = 0; j < 8; j++) acc[i][j] = 0.f;

    for (int k0 = 0; k0 < K; k0 += 8) {
        float4 av = *(const float4*)(Ap + k0);
        float4 bv = *(const float4*)(Bp + (size_t)k0 * N);
        As[aK + 0][aRow] = av.x; As[aK + 1][aRow] = av.y;
        As[aK + 2][aRow] = av.z; As[aK + 3][aRow] = av.w;
        *(float4*)&Bs[bK][bN] = bv;
        __syncthreads();
        #pragma unroll
        for (int kk = 0; kk < 8; kk++) {
            float4 a0 = *(const float4*)&As[kk][tm];
            float4 a1 = *(const float4*)&As[kk][tm + 4];
            float4 b0 = *(const float4*)&Bs[kk][tn];
            float4 b1 = *(const float4*)&Bs[kk][tn + 32];
            float a[8] = {a0.x,a0.y,a0.z,a0.w,a1.x,a1.y,a1.z,a1.w};
            float bb2[8] = {b0.x,b0.y,b0.z,b0.w,b1.x,b1.y,b1.z,b1.w};
            #pragma unroll
            for (int i = 0; i < 8; i++)
                #pragma unroll
                for (int j = 0; j < 8; j++)
                    acc[i][j] = fmaf(a[i], bb2[j], acc[i][j]);
        }
        __syncthreads();
    }

    float bb[8];
    #pragma unroll
    for (int j = 0; j < 4; j++) {
        bb[j]     = bias[n0 + tn + j];
        bb[j + 4] = bias[n0 + tn + 32 + j];
    }

    #pragma unroll
    for (int i = 0; i < 8; i++) {
        size_t off = (size_t)(m0 + tm + i) * N + n0;
        float o[8];
        #pragma unroll
        for (int j = 0; j < 8; j++) o[j] = acc[i][j] + bb[j];
        if (EPI == 2) {
            #pragma unroll
            for (int j = 0; j < 8; j++) o[j] = gelu_f(o[j]);
        }
        if (EPI == 1) {
            float4 r0 = *(const float4*)(res + off + tn);
            float4 r1 = *(const float4*)(res + off + tn + 32);
            o[0] += r0.x; o[1] += r0.y; o[2] += r0.z; o[3] += r0.w;
            o[4] += r1.x; o[5] += r1.y; o[6] += r1.z; o[7] += r1.w;
        }
        *(float4*)(C + off + tn)      = make_float4(o[0], o[1], o[2], o[3]);
        *(float4*)(C + off + tn + 32) = make_float4(o[4], o[5], o[6], o[7]);
    }
}

// ---------------- SGEMM C = A@B^T (lm_head, Bt is [N,K], N not /128) ---------
__global__ void __launch_bounds__(256) gemm_nt(
    const float* __restrict__ A, const float* __restrict__ Bt,
    float* __restrict__ C, int M, int N, int K)
{
    __shared__ float As[8][132];
    __shared__ float Bs[8][132];

    int tid = threadIdx.x;
    int m0 = blockIdx.y * 128;
    int n0 = blockIdx.x * 128;

    int aRow = tid >> 1;
    int aK   = (tid & 1) << 2;
    int bRow = tid >> 1;                  // n within tile
    int bK   = (tid & 1) << 2;

    int warp = tid >> 5, lane = tid & 31;
    int tm = ((warp >> 1) << 5) + ((lane >> 3) << 3);
    int tn = ((warp & 1) << 6) + ((lane & 7) << 2);

    const float* Ap = A + (size_t)(m0 + aRow) * K + aK;
    bool bval = (n0 + bRow) < N;
    const float* Bp = Bt + (size_t)(n0 + bRow) * K + bK;

    float acc[8][8];
    #pragma unroll
    for (int i = 0; i < 8; i++)
        #pragma unroll
        for (int j = 0; j < 8; j++) acc[i][j] = 0.f;

    for (int k0 = 0; k0 < K; k0 += 8) {
        float4 av = *(const float4*)(Ap + k0);
        float4 bv = bval ? *(const float4*)(Bp + k0) : make_float4(0.f,0.f,0.f,0.f);
        As[aK + 0][aRow] = av.x; As[aK + 1][aRow] = av.y;
        As[aK + 2][aRow] = av.z; As[aK + 3][aRow] = av.w;
        Bs[bK + 0][bRow] = bv.x; Bs[bK + 1][bRow] = bv.y;
        Bs[bK + 2][bRow] = bv.z; Bs[bK + 3][bRow] = bv.w;
        __syncthreads();
        #pragma unroll
        for (int kk = 0; kk < 8; kk++) {
            float4 a0 = *(const float4*)&As[kk][tm];
            float4 a1 = *(const float4*)&As[kk][tm + 4];
            float4 b0 = *(const float4*)&Bs[kk][tn];
            float4 b1 = *(const float4*)&Bs[kk][tn + 32];
            float a[8] = {a0.x,a0.y,a0.z,a0.w,a1.x,a1.y,a1.z,a1.w};
            float bb2[8] = {b0.x,b0.y,b0.z,b0.w,b1.x,b1.y,b1.z,b1.w};
            #pragma unroll
            for (int i = 0; i < 8; i++)
                #pragma unroll
                for (int j = 0; j < 8; j++)
                    acc[i][j] = fmaf(a[i], bb2[j], acc[i][j]);
        }
        __syncthreads();
    }

    #pragma unroll
    for (int i = 0; i < 8; i++) {
        size_t base = (size_t)(m0 + tm + i) * N;
        #pragma unroll
        for (int j = 0; j < 4; j++) {
            int n = n0 + tn + j;
            if (n < N) C[base + n] = acc[i][j];
            int n2 = n0 + tn + 32 + j;
            if (n2 < N) C[base + n2] = acc[i][j + 4];
        }
    }
}

// ---------------- attention scores: S = scale * Q K^T (causal tiles only) ----
__global__ void __launch_bounds__(256) scores_kernel(
    const float* __restrict__ qkv, float* __restrict__ scores)
{
    int qt = blockIdx.y, kt = blockIdx.x;
    if (kt > qt) return;                     // causal: untouched region never read
    int bh = blockIdx.z;
    int b = bh / H_, h = bh - b * H_;

    __shared__ float sQ[HD_][68];
    __shared__ float sK[HD_][68];

    int tid = threadIdx.x;
    const float* Qb = qkv + ((size_t)(b * S_ + qt * 64)) * (3 * D_) + h * HD_;
    const float* Kb = qkv + ((size_t)(b * S_ + kt * 64)) * (3 * D_) + D_ + h * HD_;

    #pragma unroll
    for (int i = 0; i < 4; i++) {
        int f = tid + i * 256;               // float4 index, 0..1023
        int r = f >> 4;                      // 0..63 rows
        int d4 = (f & 15) << 2;
        float4 qv = *(const float4*)(Qb + (size_t)r * (3 * D_) + d4);
        float4 kv = *(const float4*)(Kb + (size_t)r * (3 * D_) + d4);
        sQ[d4 + 0][r] = qv.x; sQ[d4 + 1][r] = qv.y; sQ[d4 + 2][r] = qv.z; sQ[d4 + 3][r] = qv.w;
        sK[d4 + 0][r] = kv.x; sK[d4 + 1][r] = kv.y; sK[d4 + 2][r] = kv.z; sK[d4 + 3][r] = kv.w;
    }
    __syncthreads();

    int warp = tid >> 5, lane = tid & 31;
    int qi = ((warp >> 1) << 4) + ((lane >> 3) << 2);
    int ki = ((warp & 1) << 5) + ((lane & 7) << 2);

    float acc[4][4] = {};
    #pragma unroll
    for (int d = 0; d < HD_; d++) {
        float4 qa = *(const float4*)&sQ[d][qi];
        float4 kb = *(const float4*)&sK[d][ki];
        float a[4] = {qa.x, qa.y, qa.z, qa.w};
        float c[4] = {kb.x, kb.y, kb.z, kb.w};
        #pragma unroll
        for (int i = 0; i < 4; i++)
            #pragma unroll
            for (int j = 0; j < 4; j++)
                acc[i][j] = fmaf(a[i], c[j], acc[i][j]);
    }

    const float scale = 0.125f;              // 1/sqrt(64)
    float* out = scores + (size_t)bh * S_ * S_ + (size_t)(qt * 64) * S_ + kt * 64;
    #pragma unroll
    for (int i = 0; i < 4; i++) {
        *(float4*)(out + (size_t)(qi + i) * S_ + ki) =
            make_float4(acc[i][0] * scale, acc[i][1] * scale,
                        acc[i][2] * scale, acc[i][3] * scale);
    }
}

// ---------------- causal softmax over valid prefix, zero the tail ------------
__global__ void __launch_bounds__(256) softmax_kernel(float* __restrict__ scores)
{
    int r = blockIdx.x;                      // bh*S + q
    int q = r & (S_ - 1);
    float* row = scores + (size_t)r * S_;
    int n = q + 1;
    int tid = threadIdx.x;

    __shared__ float red[8];
    __shared__ float s_v;

    float mx = -1e30f;
    for (int i = tid; i < n; i += 256) mx = fmaxf(mx, row[i]);
    #pragma unroll
    for (int o = 16; o; o >>= 1) mx = fmaxf(mx, __shfl_xor_sync(0xffffffffu, mx, o));
    if ((tid & 31) == 0) red[tid >> 5] = mx;
    __syncthreads();
    if (tid == 0) {
        float t = red[0];
        #pragma unroll
        for (int i = 1; i < 8; i++) t = fmaxf(t, red[i]);
        s_v = t;
    }
    __syncthreads();
    mx = s_v;
    __syncthreads();

    float e[4];
    float sum = 0.f;
    int cnt = 0;
    for (int i = tid; i < n; i += 256) { float ev = __expf(row[i] - mx); e[cnt++] = ev; sum += ev; }
    #pragma unroll
    for (int o = 16; o; o >>= 1) sum += __shfl_xor_sync(0xffffffffu, sum, o);
    if ((tid & 31) == 0) red[tid >> 5] = sum;
    __syncthreads();
    if (tid == 0) {
        float t = 0.f;
        #pragma unroll
        for (int i = 0; i < 8; i++) t += red[i];
        s_v = 1.0f / t;
    }
    __syncthreads();
    float inv = s_v;

    cnt = 0;
    for (int i = tid; i < n; i += 256) row[i] = e[cnt++] * inv;
    for (int i = n + tid; i < S_; i += 256) row[i] = 0.f;   // so PV can read full tiles
}

// ---------------- O = P @ V (causal k-tiles only) ----------------------------
__global__ void __launch_bounds__(256) pv_kernel(
    const float* __restrict__ scores, const float* __restrict__ qkv,
    float* __restrict__ attn)
{
    int qt = blockIdx.x;
    int bh = blockIdx.z;
    int b = bh / H_, h = bh - b * H_;

    __shared__ float Ps[16][68];
    __shared__ float Vs[16][64];

    int tid = threadIdx.x;
    const float* P  = scores + (size_t)bh * S_ * S_ + (size_t)(qt * 64) * S_;
    const float* Vb = qkv + (size_t)b * S_ * (3 * D_) + 2 * D_ + h * HD_;

    int warp = tid >> 5, lane = tid & 31;
    int qi = ((warp >> 1) << 4) + ((lane >> 3) << 2);
    int di = ((warp & 1) << 5) + ((lane & 7) << 2);

    int pq = tid >> 2, pk4 = (tid & 3) << 2;     // P tile 64x16
    int vk = tid >> 4, vd4 = (tid & 15) << 2;    // V tile 16x64

    float acc[4][4] = {};
    int nk = (qt + 1) * 64;                      // causal frontier
    for (int k0 = 0; k0 < nk; k0 += 16) {
        float4 pv = *(const float4*)(P + (size_t)pq * S_ + k0 + pk4);
        Ps[pk4 + 0][pq] = pv.x; Ps[pk4 + 1][pq] = pv.y;
        Ps[pk4 + 2][pq] = pv.z; Ps[pk4 + 3][pq] = pv.w;
        *(float4*)&Vs[vk][vd4] = *(const float4*)(Vb + (size_t)(k0 + vk) * (3 * D_) + vd4);
        __syncthreads();
        #pragma unroll
        for (int kk = 0; kk < 16; kk++) {
            float4 pa = *(const float4*)&Ps[kk][qi];
            float4 vv = *(const float4*)&Vs[kk][di];
            float a[4] = {pa.x, pa.y, pa.z, pa.w};
            float c[4] = {vv.x, vv.y, vv.z, vv.w};
            #pragma unroll
            for (int i = 0; i < 4; i++)
                #pragma unroll
                for (int j = 0; j < 4; j++)
                    acc[i][j] = fmaf(a[i], c[j], acc[i][j]);
        }
        __syncthreads();
    }

    float* o = attn + ((size_t)(b * S_ + qt * 64 + qi)) * D_ + h * HD_ + di;
    #pragma unroll
    for (int i = 0; i < 4; i++)
        *(float4*)(o + (size_t)i * D_) =
            make_float4(acc[i][0], acc[i][1], acc[i][2], acc[i][3]);
}

// ---------------- host orchestration -----------------------------------------
extern "C" void kernel_launch(void* const* d_in, const int* in_sizes, int n_in,
                              void* d_out, int out_size)
{
    const int*   ids  = (const int*)d_in[0];
    const float* tok  = (const float*)d_in[1];
    const float* pos  = (const float*)d_in[2];
    const float* ln1g = (const float*)d_in[3];
    const float* ln1b = (const float*)d_in[4];
    const float* qkvw = (const float*)d_in[5];
    const float* qkvb = (const float*)d_in[6];
    const float* outw = (const float*)d_in[7];
    const float* outb = (const float*)d_in[8];
    const float* ln2g = (const float*)d_in[9];
    const float* ln2b = (const float*)d_in[10];
    const float* f1w  = (const float*)d_in[11];
    const float* f1b  = (const float*)d_in[12];
    const float* f2w  = (const float*)d_in[13];
    const float* f2b  = (const float*)d_in[14];
    const float* lnfg = (const float*)d_in[15];
    const float* lnfb = (const float*)d_in[16];
    float* logits = (float*)d_out;

    float *x, *h, *qkv, *attn, *ff, *scores;
    cudaGetSymbolAddress((void**)&x,      g_x);
    cudaGetSymbolAddress((void**)&h,      g_h);
    cudaGetSymbolAddress((void**)&qkv,    g_qkv);
    cudaGetSymbolAddress((void**)&attn,   g_attn);
    cudaGetSymbolAddress((void**)&ff,     g_ff);
    cudaGetSymbolAddress((void**)&scores, g_scores);

    embed_kernel<<<(T_ * D_) / 256, 256>>>(ids, tok, pos, x);

    for (int l = 0; l < L_; l++) {
        ln_kernel<<<T_, 256>>>(x, ln1g + l * D_, ln1b + l * D_, h);

        gemm_nn<0><<<dim3((3 * D_) / 128, T_ / 128), 256>>>(
            h, qkvw + (size_t)l * D_ * 3 * D_, qkvb + (size_t)l * 3 * D_,
            nullptr, qkv, T_, 3 * D_, D_);

        scores_kernel<<<dim3(16, 16, B_ * H_), 256>>>(qkv, scores);
        softmax_kernel<<<B_ * H_ * S_, 256>>>(scores);
        pv_kernel<<<dim3(16, 1, B_ * H_), 256>>>(scores, qkv, attn);

        gemm_nn<1><<<dim3(D_ / 128, T_ / 128), 256>>>(
            attn, outw + (size_t)l * D_ * D_, outb + (size_t)l * D_,
            x, x, T_, D_, D_);

        ln_kernel<<<T_, 256>>>(x, ln2g + l * D_, ln2b + l * D_, h);

        gemm_nn<2><<<dim3(F_ / 128, T_ / 128), 256>>>(
            h, f1w + (size_t)l * D_ * F_, f1b + (size_t)l * F_,
            nullptr, ff, T_, F_, D_);

        gemm_nn<1><<<dim3(D_ / 128, T_ / 128), 256>>>(
            ff, f2w + (size_t)l * F_ * D_, f2b + (size_t)l * D_,
            x, x, T_, D_, F_);
    }

    ln_kernel<<<T_, 256>>>(x, lnfg, lnfb, h);
    gemm_nt<<<dim3((V_ + 127) / 128, T_ / 128), 256>>>(h, tok, logits, T_, V_, D_);
}

// round 10
// speedup vs baseline: 1.8775x; 1.8775x over previous
#include <cuda_runtime.h>
#include <cuda_bf16.h>
#include <math.h>
#include <stdint.h>

#define B_  4
#define S_  1024
#define D_  768
#define H_  12
#define HD_ 64
#define F_  3072
#define L_  12
#define V_  50257
#define T_  (B_*S_)

// ---------------- fp32 scratch ------------------------------------------------
__device__ float g_x[T_*D_];
__device__ float g_qkv[T_*3*D_];
__device__ float g_scores[(size_t)B_*H_*S_*S_];

// ---------------- bf16 hi/lo scratch ------------------------------------------
__device__ __nv_bfloat16 g_qkvw_h[(size_t)L_*3*D_*D_], g_qkvw_l[(size_t)L_*3*D_*D_];
__device__ __nv_bfloat16 g_outw_h[(size_t)L_*D_*D_],   g_outw_l[(size_t)L_*D_*D_];
__device__ __nv_bfloat16 g_fc1w_h[(size_t)L_*F_*D_],   g_fc1w_l[(size_t)L_*F_*D_];
__device__ __nv_bfloat16 g_fc2w_h[(size_t)L_*D_*F_],   g_fc2w_l[(size_t)L_*D_*F_];
__device__ __nv_bfloat16 g_tok_h[(size_t)V_*D_],       g_tok_l[(size_t)V_*D_];
__device__ __nv_bfloat16 g_hh[T_*D_], g_hl[T_*D_];     // LN outputs
__device__ __nv_bfloat16 g_oh[T_*D_], g_ol[T_*D_];     // attention outputs
__device__ __nv_bfloat16 g_fh[(size_t)T_*F_], g_fl[(size_t)T_*F_]; // fc1 outputs

// ---------------- PTX helpers (sm_80-era features only; compile at compute_103)
__device__ __forceinline__ uint32_t smem_u32(const void* p) {
    uint32_t a;
    asm("{ .reg .u64 t; cvta.to.shared.u64 t, %1; cvt.u32.u64 %0, t; }" : "=r"(a) : "l"(p));
    return a;
}
__device__ __forceinline__ void cp16(uint32_t dst, const void* src, uint32_t sz) {
    asm volatile("cp.async.cg.shared.global [%0], [%1], 16, %2;\n"
                 :: "r"(dst), "l"(src), "r"(sz) : "memory");
}
__device__ __forceinline__ void cp_commit()  { asm volatile("cp.async.commit_group;" ::: "memory"); }
__device__ __forceinline__ void cp_wait_all(){ asm volatile("cp.async.wait_group 0;" ::: "memory"); }
__device__ __forceinline__ void cp_wait_one(){ asm volatile("cp.async.wait_group 1;" ::: "memory"); }

#define LDSM4(r, a) \
    asm volatile("ldmatrix.sync.aligned.m8n8.x4.shared.b16 {%0,%1,%2,%3}, [%4];" \
        : "=r"((r)[0]), "=r"((r)[1]), "=r"((r)[2]), "=r"((r)[3]) : "r"(a))

#define MMA_BF16(c, a, b) \
    asm volatile("mma.sync.aligned.m16n8k16.row.col.f32.bf16.bf16.f32 " \
        "{%0,%1,%2,%3}, {%4,%5,%6,%7}, {%8,%9}, {%0,%1,%2,%3};" \
        : "+f"((c)[0]), "+f"((c)[1]), "+f"((c)[2]), "+f"((c)[3]) \
        : "r"((a)[0]), "r"((a)[1]), "r"((a)[2]), "r"((a)[3]), "r"((b)[0]), "r"((b)[1]))

__device__ __forceinline__ float gelu_f(float x) {
    float x3 = x * x * x;
    return 0.5f * x * (1.0f + tanhf(0.7978845608028654f * (x + 0.044715f * x3)));
}
__device__ __forceinline__ void split_store(float v, __nv_bfloat16* h, __nv_bfloat16* l) {
    __nv_bfloat16 hb = __float2bfloat16(v);
    *h = hb;
    *l = __float2bfloat16(v - __bfloat162float(hb));
}

// ---------------- weight conversion: W[K,N] fp32 -> [N,K] bf16 hi/lo ----------
__global__ void __launch_bounds__(256) wconv_kernel(
    const float* __restrict__ W, __nv_bfloat16* __restrict__ h,
    __nv_bfloat16* __restrict__ l, int K, int N)
{
    int z = blockIdx.z;
    W += (size_t)z * K * N; h += (size_t)z * N * K; l += (size_t)z * N * K;
    __shared__ float t[32][33];
    int n0 = blockIdx.x * 32, k0 = blockIdx.y * 32;
    int tx = threadIdx.x & 31, ty = threadIdx.x >> 5;
    #pragma unroll
    for (int r = 0; r < 32; r += 8)
        t[ty + r][tx] = W[(size_t)(k0 + ty + r) * N + n0 + tx];
    __syncthreads();
    #pragma unroll
    for (int r = 0; r < 32; r += 8) {
        size_t o = (size_t)(n0 + ty + r) * K + k0 + tx;
        split_store(t[tx][ty + r], h + o, l + o);
    }
}
__global__ void __launch_bounds__(256) tconv_kernel(
    const float* __restrict__ x, __nv_bfloat16* __restrict__ h, __nv_bfloat16* __restrict__ l)
{
    size_t i = (size_t)blockIdx.x * 256 + threadIdx.x;
    split_store(x[i], h + i, l + i);
}

// ---------------- HMMA split-bf16 GEMM: C[M,N] = A @ B^T ----------------------
// A hi/lo [M,K] bf16, B hi/lo [N,K] bf16. CTA tile 128x128, warp tile 64x32, BK=32.
// EPI: 0 bias->C  1 bias+res->C  2 bias+gelu->(Oh,Ol)  3 raw->C (guard N)
template<int EPI>
__global__ void __launch_bounds__(256) gemm_mma(
    const __nv_bfloat16* __restrict__ Ah, const __nv_bfloat16* __restrict__ Al,
    const __nv_bfloat16* __restrict__ Bh, const __nv_bfloat16* __restrict__ Bl,
    const float* __restrict__ bias, const float* __restrict__ res,
    float* __restrict__ C, __nv_bfloat16* __restrict__ Oh, __nv_bfloat16* __restrict__ Ol,
    int M, int N, int K)
{
    extern __shared__ char smem[];
    constexpr int RS = 80;               // 64 data bytes + 16 pad
    constexpr int BUF = 128 * RS;        // 10240 bytes per operand tile
    constexpr int STAGE = 4 * BUF;       // Ah, Al, Bh, Bl
    uint32_t sb = smem_u32(smem);
    int tid = threadIdx.x, wid = tid >> 5, lane = tid & 31;
    int wm = wid >> 2, wn = wid & 3;     // warp grid 2 x 4
    int n0 = blockIdx.x * 128, m0 = blockIdx.y * 128;

    const char* pAh = (const char*)(Ah + (size_t)m0 * K);
    const char* pAl = (const char*)(Al + (size_t)m0 * K);
    const char* pBh = (const char*)(Bh + (size_t)n0 * K);
    const char* pBl = (const char*)(Bl + (size_t)n0 * K);
    int nCh = K >> 5;                    // K chunks of 32

    auto load_chunk = [&](int s, int kc) {
        uint32_t base = sb + s * STAGE;
        size_t kb = (size_t)kc * 64;     // 32 bf16 = 64 bytes
        #pragma unroll
        for (int idx = tid; idx < 512; idx += 256) {   // A: 128 rows x 4 granules
            int r = idx >> 2, g = idx & 3;
            uint32_t d = base + r * RS + g * 16;
            size_t go = (size_t)r * (K * 2) + kb + g * 16;
            cp16(d,       pAh + go, 16);
            cp16(d + BUF, pAl + go, 16);
        }
        #pragma unroll
        for (int idx = tid; idx < 512; idx += 256) {   // B: 128 rows x 4 granules
            int r = idx >> 2, g = idx & 3;
            bool ok = (n0 + r) < N;
            size_t go = (size_t)(ok ? r : 0) * (K * 2) + kb + g * 16;
            uint32_t d = base + r * RS + g * 16;
            cp16(d + 2 * BUF, pBh + go, ok ? 16u : 0u);
            cp16(d + 3 * BUF, pBl + go, ok ? 16u : 0u);
        }
        cp_commit();
    };

    float acc[4][4][4];
    #pragma unroll
    for (int i = 0; i < 4; i++)
        #pragma unroll
        for (int j = 0; j < 4; j++)
            #pragma unroll
            for (int k = 0; k < 4; k++) acc[i][j][k] = 0.f;

    // ldmatrix lane addressing
    int a_row = lane & 15;
    int a_col = (lane >> 4) << 4;                      // 0 or 16 bytes (k8-15)
    int b_row = (lane & 7) + ((lane >> 4) << 3);       // n within 16-row group
    int b_col = ((lane >> 3) & 1) << 4;                // 0 or 16 bytes

    load_chunk(0, 0);
    for (int i = 0; i < nCh; i++) {
        if (i + 1 < nCh) { load_chunk((i + 1) & 1, i + 1); cp_wait_one(); }
        else             { cp_wait_all(); }
        __syncthreads();
        uint32_t base = sb + (i & 1) * STAGE;
        #pragma unroll
        for (int kk = 0; kk < 2; kk++) {               // two k16 steps
            int kb = kk * 32;
            uint32_t ah[4][4], al[4][4], bh[4][2], bl[4][2];
            #pragma unroll
            for (int mt = 0; mt < 4; mt++) {
                uint32_t ad = base + (wm * 64 + mt * 16 + a_row) * RS + kb + a_col;
                LDSM4(ah[mt], ad);
                LDSM4(al[mt], ad + BUF);
            }
            #pragma unroll
            for (int half = 0; half < 2; half++) {
                uint32_t bd = base + 2 * BUF + (wn * 32 + half * 16 + b_row) * RS + kb + b_col;
                uint32_t t[4];
                LDSM4(t, bd);
                bh[2*half][0] = t[0]; bh[2*half][1] = t[1];
                bh[2*half+1][0] = t[2]; bh[2*half+1][1] = t[3];
                LDSM4(t, bd + BUF);
                bl[2*half][0] = t[0]; bl[2*half][1] = t[1];
                bl[2*half+1][0] = t[2]; bl[2*half+1][1] = t[3];
            }
            #pragma unroll
            for (int mt = 0; mt < 4; mt++)
                #pragma unroll
                for (int nt = 0; nt < 4; nt++) {
                    MMA_BF16(acc[mt][nt], ah[mt], bh[nt]);
                    MMA_BF16(acc[mt][nt], ah[mt], bl[nt]);
                    MMA_BF16(acc[mt][nt], al[mt], bh[nt]);
                }
        }
        __syncthreads();
    }

    // ---- epilogue: direct stores, fused bias/res/gelu -------------------------
    int lr = lane >> 2, lc = (lane & 3) << 1;
    int rbase = m0 + wm * 64, cbase = n0 + wn * 32;
    #pragma unroll
    for (int mt = 0; mt < 4; mt++) {
        #pragma unroll
        for (int nt = 0; nt < 4; nt++) {
            int c = cbase + nt * 8 + lc;
            float b0 = 0.f, b1 = 0.f;
            if (EPI != 3) { b0 = bias[c]; b1 = bias[c + 1]; }
            #pragma unroll
            for (int half = 0; half < 2; half++) {
                int row = rbase + mt * 16 + lr + half * 8;
                size_t off = (size_t)row * N + c;
                float v0 = acc[mt][nt][2 * half]     + b0;
                float v1 = acc[mt][nt][2 * half + 1] + b1;
                if (EPI == 1) {
                    float2 rr = *(const float2*)(res + off);
                    v0 += rr.x; v1 += rr.y;
                }
                if (EPI == 2) {
                    v0 = gelu_f(v0); v1 = gelu_f(v1);
                    split_store(v0, Oh + off,     Ol + off);
                    split_store(v1, Oh + off + 1, Ol + off + 1);
                } else if (EPI == 3) {
                    if (c < N)     C[off]     = acc[mt][nt][2 * half];
                    if (c + 1 < N) C[off + 1] = acc[mt][nt][2 * half + 1];
                } else {
                    *(float2*)(C + off) = make_float2(v0, v1);
                }
            }
        }
    }
}

// ---------------- embedding ---------------------------------------------------
__global__ void __launch_bounds__(256) embed_kernel(
    const int* __restrict__ ids, const float* __restrict__ tok,
    const float* __restrict__ pos, float* __restrict__ x)
{
    int i = blockIdx.x * 256 + threadIdx.x;
    int d = i % D_, t = i / D_, s = t & (S_ - 1);
    x[i] = tok[(size_t)ids[t] * D_ + d] + pos[(size_t)s * D_ + d];
}

// ---------------- layernorm -> bf16 hi/lo -------------------------------------
__global__ void __launch_bounds__(256) ln_split_kernel(
    const float* __restrict__ x, const float* __restrict__ g,
    const float* __restrict__ b, __nv_bfloat16* __restrict__ oh,
    __nv_bfloat16* __restrict__ ol)
{
    int row = blockIdx.x, tid = threadIdx.x;
    const float* xr = x + (size_t)row * D_;
    float v0 = xr[tid], v1 = xr[tid + 256], v2 = xr[tid + 512];
    __shared__ float red[8];
    __shared__ float s_stat;
    float s = v0 + v1 + v2;
    #pragma unroll
    for (int o = 16; o; o >>= 1) s += __shfl_xor_sync(0xffffffffu, s, o);
    if ((tid & 31) == 0) red[tid >> 5] = s;
    __syncthreads();
    if (tid == 0) {
        float t = 0.f;
        #pragma unroll
        for (int i = 0; i < 8; i++) t += red[i];
        s_stat = t * (1.0f / D_);
    }
    __syncthreads();
    float mean = s_stat;
    __syncthreads();
    float d0 = v0 - mean, d1 = v1 - mean, d2 = v2 - mean;
    float s2 = d0*d0 + d1*d1 + d2*d2;
    #pragma unroll
    for (int o = 16; o; o >>= 1) s2 += __shfl_xor_sync(0xffffffffu, s2, o);
    if ((tid & 31) == 0) red[tid >> 5] = s2;
    __syncthreads();
    if (tid == 0) {
        float t = 0.f;
        #pragma unroll
        for (int i = 0; i < 8; i++) t += red[i];
        s_stat = rsqrtf(t * (1.0f / D_) + 1e-5f);
    }
    __syncthreads();
    float inv = s_stat;
    size_t base = (size_t)row * D_;
    split_store(g[tid]     * (d0*inv) + b[tid],     oh + base + tid,       ol + base + tid);
    split_store(g[tid+256] * (d1*inv) + b[tid+256], oh + base + tid + 256, ol + base + tid + 256);
    split_store(g[tid+512] * (d2*inv) + b[tid+512], oh + base + tid + 512, ol + base + tid + 512);
}

// ---------------- attention (fp32 SIMT) ---------------------------------------
__global__ void __launch_bounds__(256) scores_kernel(
    const float* __restrict__ qkv, float* __restrict__ scores)
{
    int qt = blockIdx.y, kt = blockIdx.x;
    if (kt > qt) return;
    int bh = blockIdx.z;
    int b = bh / H_, h = bh - b * H_;
    __shared__ float sQ[HD_][68];
    __shared__ float sK[HD_][68];
    int tid = threadIdx.x;
    const float* Qb = qkv + ((size_t)(b * S_ + qt * 64)) * (3 * D_) + h * HD_;
    const float* Kb = qkv + ((size_t)(b * S_ + kt * 64)) * (3 * D_) + D_ + h * HD_;
    #pragma unroll
    for (int i = 0; i < 4; i++) {
        int f = tid + i * 256;
        int r = f >> 4, d4 = (f & 15) << 2;
        float4 qv = *(const float4*)(Qb + (size_t)r * (3 * D_) + d4);
        float4 kv = *(const float4*)(Kb + (size_t)r * (3 * D_) + d4);
        sQ[d4+0][r] = qv.x; sQ[d4+1][r] = qv.y; sQ[d4+2][r] = qv.z; sQ[d4+3][r] = qv.w;
        sK[d4+0][r] = kv.x; sK[d4+1][r] = kv.y; sK[d4+2][r] = kv.z; sK[d4+3][r] = kv.w;
    }
    __syncthreads();
    int warp = tid >> 5, lane = tid & 31;
    int qi = ((warp >> 1) << 4) + ((lane >> 3) << 2);
    int ki = ((warp & 1) << 5) + ((lane & 7) << 2);
    float acc[4][4] = {};
    #pragma unroll
    for (int d = 0; d < HD_; d++) {
        float4 qa = *(const float4*)&sQ[d][qi];
        float4 kb = *(const float4*)&sK[d][ki];
        float a[4] = {qa.x, qa.y, qa.z, qa.w};
        float c[4] = {kb.x, kb.y, kb.z, kb.w};
        #pragma unroll
        for (int i = 0; i < 4; i++)
            #pragma unroll
            for (int j = 0; j < 4; j++)
                acc[i][j] = fmaf(a[i], c[j], acc[i][j]);
    }
    float* out = scores + (size_t)bh * S_ * S_ + (size_t)(qt * 64) * S_ + kt * 64;
    #pragma unroll
    for (int i = 0; i < 4; i++)
        *(float4*)(out + (size_t)(qi + i) * S_ + ki) =
            make_float4(acc[i][0]*0.125f, acc[i][1]*0.125f, acc[i][2]*0.125f, acc[i][3]*0.125f);
}

__global__ void __launch_bounds__(256) softmax_kernel(float* __restrict__ scores)
{
    int r = blockIdx.x;
    int q = r & (S_ - 1);
    float* row = scores + (size_t)r * S_;
    int n = q + 1, tid = threadIdx.x;
    __shared__ float red[8];
    __shared__ float s_v;
    float mx = -1e30f;
    for (int i = tid; i < n; i += 256) mx = fmaxf(mx, row[i]);
    #pragma unroll
    for (int o = 16; o; o >>= 1) mx = fmaxf(mx, __shfl_xor_sync(0xffffffffu, mx, o));
    if ((tid & 31) == 0) red[tid >> 5] = mx;
    __syncthreads();
    if (tid == 0) {
        float t = red[0];
        #pragma unroll
        for (int i = 1; i < 8; i++) t = fmaxf(t, red[i]);
        s_v = t;
    }
    __syncthreads();
    mx = s_v;
    __syncthreads();
    float e[4], sum = 0.f;
    int cnt = 0;
    for (int i = tid; i < n; i += 256) { float ev = __expf(row[i] - mx); e[cnt++] = ev; sum += ev; }
    #pragma unroll
    for (int o = 16; o; o >>= 1) sum += __shfl_xor_sync(0xffffffffu, sum, o);
    if ((tid & 31) == 0) red[tid >> 5] = sum;
    __syncthreads();
    if (tid == 0) {
        float t = 0.f;
        #pragma unroll
        for (int i = 0; i < 8; i++) t += red[i];
        s_v = 1.0f / t;
    }
    __syncthreads();
    float inv = s_v;
    cnt = 0;
    for (int i = tid; i < n; i += 256) row[i] = e[cnt++] * inv;
    for (int i = n + tid; i < S_; i += 256) row[i] = 0.f;
}

__global__ void __launch_bounds__(256) pv_kernel(
    const float* __restrict__ scores, const float* __restrict__ qkv,
    __nv_bfloat16* __restrict__ oh, __nv_bfloat16* __restrict__ ol)
{
    int qt = blockIdx.x;
    int bh = blockIdx.z;
    int b = bh / H_, h = bh - b * H_;
    __shared__ float Ps[16][68];
    __shared__ float Vs[16][64];
    int tid = threadIdx.x;
    const float* P  = scores + (size_t)bh * S_ * S_ + (size_t)(qt * 64) * S_;
    const float* Vb = qkv + (size_t)b * S_ * (3 * D_) + 2 * D_ + h * HD_;
    int warp = tid >> 5, lane = tid & 31;
    int qi = ((warp >> 1) << 4) + ((lane >> 3) << 2);
    int di = ((warp & 1) << 5) + ((lane & 7) << 2);
    int pq = tid >> 2, pk4 = (tid & 3) << 2;
    int vk = tid >> 4, vd4 = (tid & 15) << 2;
    float acc[4][4] = {};
    int nk = (qt + 1) * 64;
    for (int k0 = 0; k0 < nk; k0 += 16) {
        float4 pv = *(const float4*)(P + (size_t)pq * S_ + k0 + pk4);
        Ps[pk4+0][pq] = pv.x; Ps[pk4+1][pq] = pv.y; Ps[pk4+2][pq] = pv.z; Ps[pk4+3][pq] = pv.w;
        *(float4*)&Vs[vk][vd4] = *(const float4*)(Vb + (size_t)(k0 + vk) * (3 * D_) + vd4);
        __syncthreads();
        #pragma unroll
        for (int kk = 0; kk < 16; kk++) {
            float4 pa = *(const float4*)&Ps[kk][qi];
            float4 vv = *(const float4*)&Vs[kk][di];
            float a[4] = {pa.x, pa.y, pa.z, pa.w};
            float c[4] = {vv.x, vv.y, vv.z, vv.w};
            #pragma unroll
            for (int i = 0; i < 4; i++)
                #pragma unroll
                for (int j = 0; j < 4; j++)
                    acc[i][j] = fmaf(a[i], c[j], acc[i][j]);
        }
        __syncthreads();
    }
    size_t base = ((size_t)(b * S_ + qt * 64 + qi)) * D_ + h * HD_ + di;
    #pragma unroll
    for (int i = 0; i < 4; i++)
        #pragma unroll
        for (int j = 0; j < 4; j++)
            split_store(acc[i][j], oh + base + (size_t)i * D_ + j, ol + base + (size_t)i * D_ + j);
}

// ---------------- host orchestration ------------------------------------------
extern "C" void kernel_launch(void* const* d_in, const int* in_sizes, int n_in,
                              void* d_out, int out_size)
{
    const int*   ids  = (const int*)d_in[0];
    const float* tok  = (const float*)d_in[1];
    const float* pos  = (const float*)d_in[2];
    const float* ln1g = (const float*)d_in[3];
    const float* ln1b = (const float*)d_in[4];
    const float* qkvw = (const float*)d_in[5];
    const float* qkvb = (const float*)d_in[6];
    const float* outw = (const float*)d_in[7];
    const float* outb = (const float*)d_in[8];
    const float* ln2g = (const float*)d_in[9];
    const float* ln2b = (const float*)d_in[10];
    const float* f1w  = (const float*)d_in[11];
    const float* f1b  = (const float*)d_in[12];
    const float* f2w  = (const float*)d_in[13];
    const float* f2b  = (const float*)d_in[14];
    const float* lnfg = (const float*)d_in[15];
    const float* lnfb = (const float*)d_in[16];
    float* logits = (float*)d_out;

    float *x, *qkv, *scores;
    cudaGetSymbolAddress((void**)&x,      g_x);
    cudaGetSymbolAddress((void**)&qkv,    g_qkv);
    cudaGetSymbolAddress((void**)&scores, g_scores);
    __nv_bfloat16 *qh, *ql, *ow_h, *ow_l, *f1h, *f1l, *f2h, *f2l, *th, *tl;
    __nv_bfloat16 *hh, *hl, *oh, *ol, *fh, *fl;
    cudaGetSymbolAddress((void**)&qh,   g_qkvw_h);  cudaGetSymbolAddress((void**)&ql,   g_qkvw_l);
    cudaGetSymbolAddress((void**)&ow_h, g_outw_h);  cudaGetSymbolAddress((void**)&ow_l, g_outw_l);
    cudaGetSymbolAddress((void**)&f1h,  g_fc1w_h);  cudaGetSymbolAddress((void**)&f1l,  g_fc1w_l);
    cudaGetSymbolAddress((void**)&f2h,  g_fc2w_h);  cudaGetSymbolAddress((void**)&f2l,  g_fc2w_l);
    cudaGetSymbolAddress((void**)&th,   g_tok_h);   cudaGetSymbolAddress((void**)&tl,   g_tok_l);
    cudaGetSymbolAddress((void**)&hh,   g_hh);      cudaGetSymbolAddress((void**)&hl,   g_hl);
    cudaGetSymbolAddress((void**)&oh,   g_oh);      cudaGetSymbolAddress((void**)&ol,   g_ol);
    cudaGetSymbolAddress((void**)&fh,   g_fh);      cudaGetSymbolAddress((void**)&fl,   g_fl);

    constexpr int SMEM = 2 * 4 * 128 * 80;   // 81920 bytes (double-buffered stages)
    cudaFuncSetAttribute(gemm_mma<0>, cudaFuncAttributeMaxDynamicSharedMemorySize, SMEM);
    cudaFuncSetAttribute(gemm_mma<1>, cudaFuncAttributeMaxDynamicSharedMemorySize, SMEM);
    cudaFuncSetAttribute(gemm_mma<2>, cudaFuncAttributeMaxDynamicSharedMemorySize, SMEM);
    cudaFuncSetAttribute(gemm_mma<3>, cudaFuncAttributeMaxDynamicSharedMemorySize, SMEM);

    // one-time-per-launch weight conversion (transpose to [N,K] hi/lo)
    wconv_kernel<<<dim3(3*D_/32, D_/32, L_), 256>>>(qkvw, qh, ql, D_, 3*D_);
    wconv_kernel<<<dim3(D_/32,   D_/32, L_), 256>>>(outw, ow_h, ow_l, D_, D_);
    wconv_kernel<<<dim3(F_/32,   D_/32, L_), 256>>>(f1w, f1h, f1l, D_, F_);
    wconv_kernel<<<dim3(D_/32,   F_/32, L_), 256>>>(f2w, f2h, f2l, F_, D_);
    tconv_kernel<<<(int)(((size_t)V_*D_)/256), 256>>>(tok, th, tl);

    embed_kernel<<<(T_ * D_) / 256, 256>>>(ids, tok, pos, x);

    for (int l = 0; l < L_; l++) {
        ln_split_kernel<<<T_, 256>>>(x, ln1g + l * D_, ln1b + l * D_, hh, hl);
        gemm_mma<0><<<dim3(3*D_/128, T_/128), 256, SMEM>>>(
            hh, hl, qh + (size_t)l*3*D_*D_, ql + (size_t)l*3*D_*D_,
            qkvb + (size_t)l*3*D_, nullptr, qkv, nullptr, nullptr, T_, 3*D_, D_);

        scores_kernel<<<dim3(16, 16, B_ * H_), 256>>>(qkv, scores);
        softmax_kernel<<<B_ * H_ * S_, 256>>>(scores);
        pv_kernel<<<dim3(16, 1, B_ * H_), 256>>>(scores, qkv, oh, ol);

        gemm_mma<1><<<dim3(D_/128, T_/128), 256, SMEM>>>(
            oh, ol, ow_h + (size_t)l*D_*D_, ow_l + (size_t)l*D_*D_,
            outb + (size_t)l*D_, x, x, nullptr, nullptr, T_, D_, D_);

        ln_split_kernel<<<T_, 256>>>(x, ln2g + l * D_, ln2b + l * D_, hh, hl);
        gemm_mma<2><<<dim3(F_/128, T_/128), 256, SMEM>>>(
            hh, hl, f1h + (size_t)l*F_*D_, f1l + (size_t)l*F_*D_,
            f1b + (size_t)l*F_, nullptr, nullptr, fh, fl, T_, F_, D_);

        gemm_mma<1><<<dim3(D_/128, T_/128), 256, SMEM>>>(
            fh, fl, f2h + (size_t)l*D_*F_, f2l + (size_t)l*D_*F_,
            f2b + (size_t)l*D_, x, x, nullptr, nullptr, T_, D_, F_);
    }

    ln_split_kernel<<<T_, 256>>>(x, lnfg, lnfb, hh, hl);
    gemm_mma<3><<<dim3((V_ + 127)/128, T_/128), 256, SMEM>>>(
        hh, hl, th, tl, nullptr, nullptr, logits, nullptr, nullptr, T_, V_, D_);
}

// round 13
// speedup vs baseline: 2.1218x; 1.1301x over previous
#include <cuda_runtime.h>
#include <cuda_bf16.h>
#include <math.h>
#include <stdint.h>

#define B_  4
#define S_  1024
#define D_  768
#define H_  12
#define HD_ 64
#define F_  3072
#define L_  12
#define V_  50257
#define T_  (B_*S_)

// ---------------- fp32 scratch ------------------------------------------------
__device__ float g_x[T_*D_];
__device__ float g_qkv[T_*3*D_];
__device__ float g_scores[(size_t)B_*H_*S_*S_];

// ---------------- bf16 hi/lo scratch ------------------------------------------
__device__ __nv_bfloat16 g_qkvw_h[(size_t)L_*3*D_*D_], g_qkvw_l[(size_t)L_*3*D_*D_];
__device__ __nv_bfloat16 g_outw_h[(size_t)L_*D_*D_],   g_outw_l[(size_t)L_*D_*D_];
__device__ __nv_bfloat16 g_fc1w_h[(size_t)L_*F_*D_],   g_fc1w_l[(size_t)L_*F_*D_];
__device__ __nv_bfloat16 g_fc2w_h[(size_t)L_*D_*F_],   g_fc2w_l[(size_t)L_*D_*F_];
__device__ __nv_bfloat16 g_tok_h[(size_t)V_*D_],       g_tok_l[(size_t)V_*D_];
__device__ __nv_bfloat16 g_hh[T_*D_], g_hl[T_*D_];     // LN outputs
__device__ __nv_bfloat16 g_oh[T_*D_], g_ol[T_*D_];     // attention outputs
__device__ __nv_bfloat16 g_fh[(size_t)T_*F_], g_fl[(size_t)T_*F_]; // fc1 outputs

// ---------------- PTX helpers (sm_80-era features only) ------------------------
__device__ __forceinline__ uint32_t smem_u32(const void* p) {
    uint32_t a;
    asm("{ .reg .u64 t; cvta.to.shared.u64 t, %1; cvt.u32.u64 %0, t; }" : "=r"(a) : "l"(p));
    return a;
}
__device__ __forceinline__ void cp16(uint32_t dst, const void* src, uint32_t sz) {
    asm volatile("cp.async.cg.shared.global [%0], [%1], 16, %2;\n"
                 :: "r"(dst), "l"(src), "r"(sz) : "memory");
}
__device__ __forceinline__ void cp_commit()  { asm volatile("cp.async.commit_group;" ::: "memory"); }
__device__ __forceinline__ void cp_wait_all(){ asm volatile("cp.async.wait_group 0;" ::: "memory"); }
__device__ __forceinline__ void cp_wait_one(){ asm volatile("cp.async.wait_group 1;" ::: "memory"); }

#define LDSM4(r, a) \
    asm volatile("ldmatrix.sync.aligned.m8n8.x4.shared.b16 {%0,%1,%2,%3}, [%4];" \
        : "=r"((r)[0]), "=r"((r)[1]), "=r"((r)[2]), "=r"((r)[3]) : "r"(a))

#define MMA_BF16(c, a, b) \
    asm volatile("mma.sync.aligned.m16n8k16.row.col.f32.bf16.bf16.f32 " \
        "{%0,%1,%2,%3}, {%4,%5,%6,%7}, {%8,%9}, {%0,%1,%2,%3};" \
        : "+f"((c)[0]), "+f"((c)[1]), "+f"((c)[2]), "+f"((c)[3]) \
        : "r"((a)[0]), "r"((a)[1]), "r"((a)[2]), "r"((a)[3]), "r"((b)[0]), "r"((b)[1]))

__device__ __forceinline__ float gelu_f(float x) {
    float x3 = x * x * x;
    return 0.5f * x * (1.0f + tanhf(0.7978845608028654f * (x + 0.044715f * x3)));
}
__device__ __forceinline__ void split_store(float v, __nv_bfloat16* h, __nv_bfloat16* l) {
    __nv_bfloat16 hb = __float2bfloat16(v);
    *h = hb;
    *l = __float2bfloat16(v - __bfloat162float(hb));
}

// ---------------- weight conversion: W[K,N] fp32 -> [N,K] bf16 hi/lo ----------
__global__ void __launch_bounds__(256) wconv_kernel(
    const float* __restrict__ W, __nv_bfloat16* __restrict__ h,
    __nv_bfloat16* __restrict__ l, int K, int N)
{
    int z = blockIdx.z;
    W += (size_t)z * K * N; h += (size_t)z * N * K; l += (size_t)z * N * K;
    __shared__ float t[32][33];
    int n0 = blockIdx.x * 32, k0 = blockIdx.y * 32;
    int tx = threadIdx.x & 31, ty = threadIdx.x >> 5;
    #pragma unroll
    for (int r = 0; r < 32; r += 8)
        t[ty + r][tx] = W[(size_t)(k0 + ty + r) * N + n0 + tx];
    __syncthreads();
    #pragma unroll
    for (int r = 0; r < 32; r += 8) {
        size_t o = (size_t)(n0 + ty + r) * K + k0 + tx;
        split_store(t[tx][ty + r], h + o, l + o);
    }
}
__global__ void __launch_bounds__(256) tconv_kernel(
    const float* __restrict__ x, __nv_bfloat16* __restrict__ h, __nv_bfloat16* __restrict__ l)
{
    size_t i = (size_t)blockIdx.x * 256 + threadIdx.x;
    split_store(x[i], h + i, l + i);
}

// ---------------- HMMA split-bf16 GEMM: C[M,N] = A @ B^T ----------------------
// A hi/lo [M,K] bf16, B hi/lo [N,K] bf16. CTA tile 128x128, warp tile 64x32, BK=32.
// Smem: 64B rows, XOR swizzle (chunk ^= (row>>1)&3) -> conflict-free ldmatrix,
// 64KB total double-buffered -> 2 CTAs/SM.
// EPI: 0 bias->C  1 bias+res->C  2 bias+gelu->(Oh,Ol)  3 raw->C (guard N)
#define SWIZ(r, c) ((c) ^ (((r) >> 1) & 3))
template<int EPI>
__global__ void __launch_bounds__(256, 2) gemm_mma(
    const __nv_bfloat16* __restrict__ Ah, const __nv_bfloat16* __restrict__ Al,
    const __nv_bfloat16* __restrict__ Bh, const __nv_bfloat16* __restrict__ Bl,
    const float* __restrict__ bias, const float* __restrict__ res,
    float* __restrict__ C, __nv_bfloat16* __restrict__ Oh, __nv_bfloat16* __restrict__ Ol,
    int M, int N, int K)
{
    extern __shared__ char smem[];
    constexpr int RS = 64;               // 64 data bytes per row, swizzled
    constexpr int BUF = 128 * RS;        // 8192 bytes per operand tile
    constexpr int STAGE = 4 * BUF;       // Ah, Al, Bh, Bl = 32KB
    uint32_t sb = smem_u32(smem);
    int tid = threadIdx.x, wid = tid >> 5, lane = tid & 31;
    int wm = wid >> 2, wn = wid & 3;     // warp grid 2 x 4
    int n0 = blockIdx.x * 128, m0 = blockIdx.y * 128;

    const char* pAh = (const char*)(Ah + (size_t)m0 * K);
    const char* pAl = (const char*)(Al + (size_t)m0 * K);
    const char* pBh = (const char*)(Bh + (size_t)n0 * K);
    const char* pBl = (const char*)(Bl + (size_t)n0 * K);
    int nCh = K >> 5;                    // K chunks of 32

    auto load_chunk = [&](int s, int kc) {
        uint32_t base = sb + s * STAGE;
        size_t kb = (size_t)kc * 64;     // 32 bf16 = 64 bytes
        #pragma unroll
        for (int idx = tid; idx < 512; idx += 256) {   // A: 128 rows x 4 granules
            int r = idx >> 2, g = idx & 3;
            uint32_t d = base + r * RS + SWIZ(r, g) * 16;
            size_t go = (size_t)r * (K * 2) + kb + g * 16;
            cp16(d,       pAh + go, 16);
            cp16(d + BUF, pAl + go, 16);
        }
        #pragma unroll
        for (int idx = tid; idx < 512; idx += 256) {   // B: 128 rows x 4 granules
            int r = idx >> 2, g = idx & 3;
            bool ok = (n0 + r) < N;
            size_t go = (size_t)(ok ? r : 0) * (K * 2) + kb + g * 16;
            uint32_t d = base + r * RS + SWIZ(r, g) * 16;
            cp16(d + 2 * BUF, pBh + go, ok ? 16u : 0u);
            cp16(d + 3 * BUF, pBl + go, ok ? 16u : 0u);
        }
        cp_commit();
    };

    float acc[4][4][4];
    #pragma unroll
    for (int i = 0; i < 4; i++)
        #pragma unroll
        for (int j = 0; j < 4; j++)
            #pragma unroll
            for (int k = 0; k < 4; k++) acc[i][j][k] = 0.f;

    // ldmatrix lane addressing (row, chunk index before swizzle)
    int a_row = lane & 15;
    int a_ch  = lane >> 4;                             // 0 or 1 (k-lo / k-hi 16B)
    int b_row = (lane & 7) + ((lane >> 4) << 3);
    int b_ch  = (lane >> 3) & 1;

    load_chunk(0, 0);
    for (int i = 0; i < nCh; i++) {
        if (i + 1 < nCh) { load_chunk((i + 1) & 1, i + 1); cp_wait_one(); }
        else             { cp_wait_all(); }
        __syncthreads();
        uint32_t base = sb + (i & 1) * STAGE;
        #pragma unroll
        for (int kk = 0; kk < 2; kk++) {               // two k16 steps
            int ch0 = kk * 2;                          // chunk base for this k16
            // B fragments first (held live across mt loop)
            uint32_t bh[4][2], bl[4][2];
            #pragma unroll
            for (int half = 0; half < 2; half++) {
                int r = wn * 32 + half * 16 + b_row;
                uint32_t bd = base + 2 * BUF + r * RS + SWIZ(r, ch0 + b_ch) * 16;
                uint32_t t[4];
                LDSM4(t, bd);
                bh[2*half][0] = t[0]; bh[2*half][1] = t[1];
                bh[2*half+1][0] = t[2]; bh[2*half+1][1] = t[3];
                LDSM4(t, bd + BUF);
                bl[2*half][0] = t[0]; bl[2*half][1] = t[1];
                bl[2*half+1][0] = t[2]; bl[2*half+1][1] = t[3];
            }
            // A fragments per mt (keeps live register set small)
            #pragma unroll
            for (int mt = 0; mt < 4; mt++) {
                int r = wm * 64 + mt * 16 + a_row;
                uint32_t ad = base + r * RS + SWIZ(r, ch0 + a_ch) * 16;
                uint32_t ah[4], al[4];
                LDSM4(ah, ad);
                LDSM4(al, ad + BUF);
                #pragma unroll
                for (int nt = 0; nt < 4; nt++) {
                    MMA_BF16(acc[mt][nt], ah, bh[nt]);
                    MMA_BF16(acc[mt][nt], ah, bl[nt]);
                    MMA_BF16(acc[mt][nt], al, bh[nt]);
                }
            }
        }
        __syncthreads();
    }

    // ---- epilogue: direct stores, fused bias/res/gelu -------------------------
    int lr = lane >> 2, lc = (lane & 3) << 1;
    int rbase = m0 + wm * 64, cbase = n0 + wn * 32;
    #pragma unroll
    for (int mt = 0; mt < 4; mt++) {
        #pragma unroll
        for (int nt = 0; nt < 4; nt++) {
            int c = cbase + nt * 8 + lc;
            float b0 = 0.f, b1 = 0.f;
            if (EPI != 3) { b0 = bias[c]; b1 = bias[c + 1]; }
            #pragma unroll
            for (int half = 0; half < 2; half++) {
                int row = rbase + mt * 16 + lr + half * 8;
                size_t off = (size_t)row * N + c;
                float v0 = acc[mt][nt][2 * half]     + b0;
                float v1 = acc[mt][nt][2 * half + 1] + b1;
                if (EPI == 1) {
                    float2 rr = *(const float2*)(res + off);
                    v0 += rr.x; v1 += rr.y;
                }
                if (EPI == 2) {
                    v0 = gelu_f(v0); v1 = gelu_f(v1);
                    split_store(v0, Oh + off,     Ol + off);
                    split_store(v1, Oh + off + 1, Ol + off + 1);
                } else if (EPI == 3) {
                    if (c < N)     C[off]     = acc[mt][nt][2 * half];
                    if (c + 1 < N) C[off + 1] = acc[mt][nt][2 * half + 1];
                } else {
                    *(float2*)(C + off) = make_float2(v0, v1);
                }
            }
        }
    }
}

// ---------------- embedding ---------------------------------------------------
__global__ void __launch_bounds__(256) embed_kernel(
    const int* __restrict__ ids, const float* __restrict__ tok,
    const float* __restrict__ pos, float* __restrict__ x)
{
    int i = blockIdx.x * 256 + threadIdx.x;
    int d = i % D_, t = i / D_, s = t & (S_ - 1);
    x[i] = tok[(size_t)ids[t] * D_ + d] + pos[(size_t)s * D_ + d];
}

// ---------------- layernorm -> bf16 hi/lo -------------------------------------
__global__ void __launch_bounds__(256) ln_split_kernel(
    const float* __restrict__ x, const float* __restrict__ g,
    const float* __restrict__ b, __nv_bfloat16* __restrict__ oh,
    __nv_bfloat16* __restrict__ ol)
{
    int row = blockIdx.x, tid = threadIdx.x;
    const float* xr = x + (size_t)row * D_;
    float v0 = xr[tid], v1 = xr[tid + 256], v2 = xr[tid + 512];
    __shared__ float red[8];
    __shared__ float s_stat;
    float s = v0 + v1 + v2;
    #pragma unroll
    for (int o = 16; o; o >>= 1) s += __shfl_xor_sync(0xffffffffu, s, o);
    if ((tid & 31) == 0) red[tid >> 5] = s;
    __syncthreads();
    if (tid == 0) {
        float t = 0.f;
        #pragma unroll
        for (int i = 0; i < 8; i++) t += red[i];
        s_stat = t * (1.0f / D_);
    }
    __syncthreads();
    float mean = s_stat;
    __syncthreads();
    float d0 = v0 - mean, d1 = v1 - mean, d2 = v2 - mean;
    float s2 = d0*d0 + d1*d1 + d2*d2;
    #pragma unroll
    for (int o = 16; o; o >>= 1) s2 += __shfl_xor_sync(0xffffffffu, s2, o);
    if ((tid & 31) == 0) red[tid >> 5] = s2;
    __syncthreads();
    if (tid == 0) {
        float t = 0.f;
        #pragma unroll
        for (int i = 0; i < 8; i++) t += red[i];
        s_stat = rsqrtf(t * (1.0f / D_) + 1e-5f);
    }
    __syncthreads();
    float inv = s_stat;
    size_t base = (size_t)row * D_;
    split_store(g[tid]     * (d0*inv) + b[tid],     oh + base + tid,       ol + base + tid);
    split_store(g[tid+256] * (d1*inv) + b[tid+256], oh + base + tid + 256, ol + base + tid + 256);
    split_store(g[tid+512] * (d2*inv) + b[tid+512], oh + base + tid + 512, ol + base + tid + 512);
}

// ---------------- attention (fp32 SIMT) ---------------------------------------
__global__ void __launch_bounds__(256) scores_kernel(
    const float* __restrict__ qkv, float* __restrict__ scores)
{
    int qt = blockIdx.y, kt = blockIdx.x;
    if (kt > qt) return;
    int bh = blockIdx.z;
    int b = bh / H_, h = bh - b * H_;
    __shared__ float sQ[HD_][68];
    __shared__ float sK[HD_][68];
    int tid = threadIdx.x;
    const float* Qb = qkv + ((size_t)(b * S_ + qt * 64)) * (3 * D_) + h * HD_;
    const float* Kb = qkv + ((size_t)(b * S_ + kt * 64)) * (3 * D_) + D_ + h * HD_;
    #pragma unroll
    for (int i = 0; i < 4; i++) {
        int f = tid + i * 256;
        int r = f >> 4, d4 = (f & 15) << 2;
        float4 qv = *(const float4*)(Qb + (size_t)r * (3 * D_) + d4);
        float4 kv = *(const float4*)(Kb + (size_t)r * (3 * D_) + d4);
        sQ[d4+0][r] = qv.x; sQ[d4+1][r] = qv.y; sQ[d4+2][r] = qv.z; sQ[d4+3][r] = qv.w;
        sK[d4+0][r] = kv.x; sK[d4+1][r] = kv.y; sK[d4+2][r] = kv.z; sK[d4+3][r] = kv.w;
    }
    __syncthreads();
    int warp = tid >> 5, lane = tid & 31;
    int qi = ((warp >> 1) << 4) + ((lane >> 3) << 2);
    int ki = ((warp & 1) << 5) + ((lane & 7) << 2);
    float acc[4][4] = {};
    #pragma unroll
    for (int d = 0; d < HD_; d++) {
        float4 qa = *(const float4*)&sQ[d][qi];
        float4 kb = *(const float4*)&sK[d][ki];
        float a[4] = {qa.x, qa.y, qa.z, qa.w};
        float c[4] = {kb.x, kb.y, kb.z, kb.w};
        #pragma unroll
        for (int i = 0; i < 4; i++)
            #pragma unroll
            for (int j = 0; j < 4; j++)
                acc[i][j] = fmaf(a[i], c[j], acc[i][j]);
    }
    float* out = scores + (size_t)bh * S_ * S_ + (size_t)(qt * 64) * S_ + kt * 64;
    #pragma unroll
    for (int i = 0; i < 4; i++)
        *(float4*)(out + (size_t)(qi + i) * S_ + ki) =
            make_float4(acc[i][0]*0.125f, acc[i][1]*0.125f, acc[i][2]*0.125f, acc[i][3]*0.125f);
}

__global__ void __launch_bounds__(256) softmax_kernel(float* __restrict__ scores)
{
    int r = blockIdx.x;
    int q = r & (S_ - 1);
    float* row = scores + (size_t)r * S_;
    int n = q + 1, tid = threadIdx.x;
    __shared__ float red[8];
    __shared__ float s_v;
    float mx = -1e30f;
    for (int i = tid; i < n; i += 256) mx = fmaxf(mx, row[i]);
    #pragma unroll
    for (int o = 16; o; o >>= 1) mx = fmaxf(mx, __shfl_xor_sync(0xffffffffu, mx, o));
    if ((tid & 31) == 0) red[tid >> 5] = mx;
    __syncthreads();
    if (tid == 0) {
        float t = red[0];
        #pragma unroll
        for (int i = 1; i < 8; i++) t = fmaxf(t, red[i]);
        s_v = t;
    }
    __syncthreads();
    mx = s_v;
    __syncthreads();
    float e[4], sum = 0.f;
    int cnt = 0;
    for (int i = tid; i < n; i += 256) { float ev = __expf(row[i] - mx); e[cnt++] = ev; sum += ev; }
    #pragma unroll
    for (int o = 16; o; o >>= 1) sum += __shfl_xor_sync(0xffffffffu, sum, o);
    if ((tid & 31) == 0) red[tid >> 5] = sum;
    __syncthreads();
    if (tid == 0) {
        float t = 0.f;
        #pragma unroll
        for (int i = 0; i < 8; i++) t += red[i];
        s_v = 1.0f / t;
    }
    __syncthreads();
    float inv = s_v;
    cnt = 0;
    for (int i = tid; i < n; i += 256) row[i] = e[cnt++] * inv;
    int end = ((q >> 6) + 1) << 6;            // pv only reads up to the causal tile edge
    for (int i = n + tid; i < end; i += 256) row[i] = 0.f;
}

__global__ void __launch_bounds__(256) pv_kernel(
    const float* __restrict__ scores, const float* __restrict__ qkv,
    __nv_bfloat16* __restrict__ oh, __nv_bfloat16* __restrict__ ol)
{
    int qt = blockIdx.x;
    int bh = blockIdx.z;
    int b = bh / H_, h = bh - b * H_;
    __shared__ float Ps[16][68];
    __shared__ float Vs[16][64];
    int tid = threadIdx.x;
    const float* P  = scores + (size_t)bh * S_ * S_ + (size_t)(qt * 64) * S_;
    const float* Vb = qkv + (size_t)b * S_ * (3 * D_) + 2 * D_ + h * HD_;
    int warp = tid >> 5, lane = tid & 31;
    int qi = ((warp >> 1) << 4) + ((lane >> 3) << 2);
    int di = ((warp & 1) << 5) + ((lane & 7) << 2);
    int pq = tid >> 2, pk4 = (tid & 3) << 2;
    int vk = tid >> 4, vd4 = (tid & 15) << 2;
    float acc[4][4] = {};
    int nk = (qt + 1) * 64;
    for (int k0 = 0; k0 < nk; k0 += 16) {
        float4 pv = *(const float4*)(P + (size_t)pq * S_ + k0 + pk4);
        Ps[pk4+0][pq] = pv.x; Ps[pk4+1][pq] = pv.y; Ps[pk4+2][pq] = pv.z; Ps[pk4+3][pq] = pv.w;
        *(float4*)&Vs[vk][vd4] = *(const float4*)(Vb + (size_t)(k0 + vk) * (3 * D_) + vd4);
        __syncthreads();
        #pragma unroll
        for (int kk = 0; kk < 16; kk++) {
            float4 pa = *(const float4*)&Ps[kk][qi];
            float4 vv = *(const float4*)&Vs[kk][di];
            float a[4] = {pa.x, pa.y, pa.z, pa.w};
            float c[4] = {vv.x, vv.y, vv.z, vv.w};
            #pragma unroll
            for (int i = 0; i < 4; i++)
                #pragma unroll
                for (int j = 0; j < 4; j++)
                    acc[i][j] = fmaf(a[i], c[j], acc[i][j]);
        }
        __syncthreads();
    }
    size_t base = ((size_t)(b * S_ + qt * 64 + qi)) * D_ + h * HD_ + di;
    #pragma unroll
    for (int i = 0; i < 4; i++)
        #pragma unroll
        for (int j = 0; j < 4; j++)
            split_store(acc[i][j], oh + base + (size_t)i * D_ + j, ol + base + (size_t)i * D_ + j);
}

// ---------------- host orchestration ------------------------------------------
extern "C" void kernel_launch(void* const* d_in, const int* in_sizes, int n_in,
                              void* d_out, int out_size)
{
    const int*   ids  = (const int*)d_in[0];
    const float* tok  = (const float*)d_in[1];
    const float* pos  = (const float*)d_in[2];
    const float* ln1g = (const float*)d_in[3];
    const float* ln1b = (const float*)d_in[4];
    const float* qkvw = (const float*)d_in[5];
    const float* qkvb = (const float*)d_in[6];
    const float* outw = (const float*)d_in[7];
    const float* outb = (const float*)d_in[8];
    const float* ln2g = (const float*)d_in[9];
    const float* ln2b = (const float*)d_in[10];
    const float* f1w  = (const float*)d_in[11];
    const float* f1b  = (const float*)d_in[12];
    const float* f2w  = (const float*)d_in[13];
    const float* f2b  = (const float*)d_in[14];
    const float* lnfg = (const float*)d_in[15];
    const float* lnfb = (const float*)d_in[16];
    float* logits = (float*)d_out;

    float *x, *qkv, *scores;
    cudaGetSymbolAddress((void**)&x,      g_x);
    cudaGetSymbolAddress((void**)&qkv,    g_qkv);
    cudaGetSymbolAddress((void**)&scores, g_scores);
    __nv_bfloat16 *qh, *ql, *ow_h, *ow_l, *f1h, *f1l, *f2h, *f2l, *th, *tl;
    __nv_bfloat16 *hh, *hl, *oh, *ol, *fh, *fl;
    cudaGetSymbolAddress((void**)&qh,   g_qkvw_h);  cudaGetSymbolAddress((void**)&ql,   g_qkvw_l);
    cudaGetSymbolAddress((void**)&ow_h, g_outw_h);  cudaGetSymbolAddress((void**)&ow_l, g_outw_l);
    cudaGetSymbolAddress((void**)&f1h,  g_fc1w_h);  cudaGetSymbolAddress((void**)&f1l,  g_fc1w_l);
    cudaGetSymbolAddress((void**)&f2h,  g_fc2w_h);  cudaGetSymbolAddress((void**)&f2l,  g_fc2w_l);
    cudaGetSymbolAddress((void**)&th,   g_tok_h);   cudaGetSymbolAddress((void**)&tl,   g_tok_l);
    cudaGetSymbolAddress((void**)&hh,   g_hh);      cudaGetSymbolAddress((void**)&hl,   g_hl);
    cudaGetSymbolAddress((void**)&oh,   g_oh);      cudaGetSymbolAddress((void**)&ol,   g_ol);
    cudaGetSymbolAddress((void**)&fh,   g_fh);      cudaGetSymbolAddress((void**)&fl,   g_fl);

    constexpr int SMEM = 2 * 4 * 128 * 64;   // 65536 bytes (double-buffered, swizzled)
    cudaFuncSetAttribute(gemm_mma<0>, cudaFuncAttributeMaxDynamicSharedMemorySize, SMEM);
    cudaFuncSetAttribute(gemm_mma<1>, cudaFuncAttributeMaxDynamicSharedMemorySize, SMEM);
    cudaFuncSetAttribute(gemm_mma<2>, cudaFuncAttributeMaxDynamicSharedMemorySize, SMEM);
    cudaFuncSetAttribute(gemm_mma<3>, cudaFuncAttributeMaxDynamicSharedMemorySize, SMEM);

    // one-time-per-launch weight conversion (transpose to [N,K] hi/lo)
    wconv_kernel<<<dim3(3*D_/32, D_/32, L_), 256>>>(qkvw, qh, ql, D_, 3*D_);
    wconv_kernel<<<dim3(D_/32,   D_/32, L_), 256>>>(outw, ow_h, ow_l, D_, D_);
    wconv_kernel<<<dim3(F_/32,   D_/32, L_), 256>>>(f1w, f1h, f1l, D_, F_);
    wconv_kernel<<<dim3(D_/32,   F_/32, L_), 256>>>(f2w, f2h, f2l, F_, D_);
    tconv_kernel<<<(int)(((size_t)V_*D_)/256), 256>>>(tok, th, tl);

    embed_kernel<<<(T_ * D_) / 256, 256>>>(ids, tok, pos, x);

    for (int l = 0; l < L_; l++) {
        ln_split_kernel<<<T_, 256>>>(x, ln1g + l * D_, ln1b + l * D_, hh, hl);
        gemm_mma<0><<<dim3(3*D_/128, T_/128), 256, SMEM>>>(
            hh, hl, qh + (size_t)l*3*D_*D_, ql + (size_t)l*3*D_*D_,
            qkvb + (size_t)l*3*D_, nullptr, qkv, nullptr, nullptr, T_, 3*D_, D_);

        scores_kernel<<<dim3(16, 16, B_ * H_), 256>>>(qkv, scores);
        softmax_kernel<<<B_ * H_ * S_, 256>>>(scores);
        pv_kernel<<<dim3(16, 1, B_ * H_), 256>>>(scores, qkv, oh, ol);

        gemm_mma<1><<<dim3(D_/128, T_/128), 256, SMEM>>>(
            oh, ol, ow_h + (size_t)l*D_*D_, ow_l + (size_t)l*D_*D_,
            outb + (size_t)l*D_, x, x, nullptr, nullptr, T_, D_, D_);

        ln_split_kernel<<<T_, 256>>>(x, ln2g + l * D_, ln2b + l * D_, hh, hl);
        gemm_mma<2><<<dim3(F_/128, T_/128), 256, SMEM>>>(
            hh, hl, f1h + (size_t)l*F_*D_, f1l + (size_t)l*F_*D_,
            f1b + (size_t)l*F_, nullptr, nullptr, fh, fl, T_, F_, D_);

        gemm_mma<1><<<dim3(D_/128, T_/128), 256, SMEM>>>(
            fh, fl, f2h + (size_t)l*D_*F_, f2l + (size_t)l*D_*F_,
            f2b + (size_t)l*D_, x, x, nullptr, nullptr, T_, D_, F_);
    }

    ln_split_kernel<<<T_, 256>>>(x, lnfg, lnfb, hh, hl);
    gemm_mma<3><<<dim3((V_ + 127)/128, T_/128), 256, SMEM>>>(
        hh, hl, th, tl, nullptr, nullptr, logits, nullptr, nullptr, T_, V_, D_);
}

// round 15
// speedup vs baseline: 2.5600x; 1.2065x over previous
#include <cuda_runtime.h>
#include <cuda_bf16.h>
#include <math.h>
#include <stdint.h>

#define B_  4
#define S_  1024
#define D_  768
#define H_  12
#define HD_ 64
#define F_  3072
#define L_  12
#define V_  50257
#define T_  (B_*S_)

// ---------------- fp32 scratch ------------------------------------------------
__device__ float g_x[T_*D_];
__device__ float g_qkv[T_*3*D_];

// ---------------- bf16 hi/lo scratch ------------------------------------------
__device__ __nv_bfloat16 g_qkvw_h[(size_t)L_*3*D_*D_], g_qkvw_l[(size_t)L_*3*D_*D_];
__device__ __nv_bfloat16 g_outw_h[(size_t)L_*D_*D_],   g_outw_l[(size_t)L_*D_*D_];
__device__ __nv_bfloat16 g_fc1w_h[(size_t)L_*F_*D_],   g_fc1w_l[(size_t)L_*F_*D_];
__device__ __nv_bfloat16 g_fc2w_h[(size_t)L_*D_*F_],   g_fc2w_l[(size_t)L_*D_*F_];
__device__ __nv_bfloat16 g_tok_h[(size_t)V_*D_],       g_tok_l[(size_t)V_*D_];
__device__ __nv_bfloat16 g_hh[T_*D_], g_hl[T_*D_];     // LN outputs
__device__ __nv_bfloat16 g_oh[T_*D_], g_ol[T_*D_];     // attention outputs
__device__ __nv_bfloat16 g_fh[(size_t)T_*F_], g_fl[(size_t)T_*F_]; // fc1 outputs

// ---------------- PTX helpers (sm_80-era features only) ------------------------
__device__ __forceinline__ uint32_t smem_u32(const void* p) {
    uint32_t a;
    asm("{ .reg .u64 t; cvta.to.shared.u64 t, %1; cvt.u32.u64 %0, t; }" : "=r"(a) : "l"(p));
    return a;
}
__device__ __forceinline__ void cp16(uint32_t dst, const void* src, uint32_t sz) {
    asm volatile("cp.async.cg.shared.global [%0], [%1], 16, %2;\n"
                 :: "r"(dst), "l"(src), "r"(sz) : "memory");
}
__device__ __forceinline__ void cp_commit()  { asm volatile("cp.async.commit_group;" ::: "memory"); }
__device__ __forceinline__ void cp_wait_all(){ asm volatile("cp.async.wait_group 0;" ::: "memory"); }
__device__ __forceinline__ void cp_wait_one(){ asm volatile("cp.async.wait_group 1;" ::: "memory"); }

#define LDSM4(r, a) \
    asm volatile("ldmatrix.sync.aligned.m8n8.x4.shared.b16 {%0,%1,%2,%3}, [%4];" \
        : "=r"((r)[0]), "=r"((r)[1]), "=r"((r)[2]), "=r"((r)[3]) : "r"(a))

#define MMA_BF16(c, a, b) \
    asm volatile("mma.sync.aligned.m16n8k16.row.col.f32.bf16.bf16.f32 " \
        "{%0,%1,%2,%3}, {%4,%5,%6,%7}, {%8,%9}, {%0,%1,%2,%3};" \
        : "+f"((c)[0]), "+f"((c)[1]), "+f"((c)[2]), "+f"((c)[3]) \
        : "r"((a)[0]), "r"((a)[1]), "r"((a)[2]), "r"((a)[3]), "r"((b)[0]), "r"((b)[1]))

__device__ __forceinline__ float gelu_f(float x) {
    float x3 = x * x * x;
    return 0.5f * x * (1.0f + tanhf(0.7978845608028654f * (x + 0.044715f * x3)));
}
__device__ __forceinline__ void split_store(float v, __nv_bfloat16* h, __nv_bfloat16* l) {
    __nv_bfloat16 hb = __float2bfloat16(v);
    *h = hb;
    *l = __float2bfloat16(v - __bfloat162float(hb));
}
__device__ __forceinline__ void split_smem(float v, __nv_bfloat16* h, __nv_bfloat16* l) {
    __nv_bfloat16 hb = __float2bfloat16(v);
    *h = hb;
    *l = __float2bfloat16(v - __bfloat162float(hb));
}
// pack two fp32 into bf16x2 hi word + lo word (low 16 bits = first element)
__device__ __forceinline__ void split_pack2(float a, float b, uint32_t& hi, uint32_t& lo) {
    __nv_bfloat16 ah = __float2bfloat16(a), bh = __float2bfloat16(b);
    __nv_bfloat16 al = __float2bfloat16(a - __bfloat162float(ah));
    __nv_bfloat16 bl = __float2bfloat16(b - __bfloat162float(bh));
    hi = (uint32_t)__bfloat16_as_ushort(ah) | ((uint32_t)__bfloat16_as_ushort(bh) << 16);
    lo = (uint32_t)__bfloat16_as_ushort(al) | ((uint32_t)__bfloat16_as_ushort(bl) << 16);
}
__device__ __forceinline__ uint32_t pack_bf16x2(float a, float b) {
    __nv_bfloat16 ah = __float2bfloat16(a), bh = __float2bfloat16(b);
    return (uint32_t)__bfloat16_as_ushort(ah) | ((uint32_t)__bfloat16_as_ushort(bh) << 16);
}

// ---------------- weight conversion: W[K,N] fp32 -> [N,K] bf16 hi/lo ----------
__global__ void __launch_bounds__(256) wconv_kernel(
    const float* __restrict__ W, __nv_bfloat16* __restrict__ h,
    __nv_bfloat16* __restrict__ l, int K, int N)
{
    int z = blockIdx.z;
    W += (size_t)z * K * N; h += (size_t)z * N * K; l += (size_t)z * N * K;
    __shared__ float t[32][33];
    int n0 = blockIdx.x * 32, k0 = blockIdx.y * 32;
    int tx = threadIdx.x & 31, ty = threadIdx.x >> 5;
    #pragma unroll
    for (int r = 0; r < 32; r += 8)
        t[ty + r][tx] = W[(size_t)(k0 + ty + r) * N + n0 + tx];
    __syncthreads();
    #pragma unroll
    for (int r = 0; r < 32; r += 8) {
        size_t o = (size_t)(n0 + ty + r) * K + k0 + tx;
        split_store(t[tx][ty + r], h + o, l + o);
    }
}
__global__ void __launch_bounds__(256) tconv_kernel(
    const float* __restrict__ x, __nv_bfloat16* __restrict__ h, __nv_bfloat16* __restrict__ l)
{
    size_t i = (size_t)blockIdx.x * 256 + threadIdx.x;
    split_store(x[i], h + i, l + i);
}

// ---------------- HMMA split-bf16 GEMM (unchanged from R13) --------------------
#define SWIZ(r, c) ((c) ^ (((r) >> 1) & 3))
template<int EPI>
__global__ void __launch_bounds__(256, 2) gemm_mma(
    const __nv_bfloat16* __restrict__ Ah, const __nv_bfloat16* __restrict__ Al,
    const __nv_bfloat16* __restrict__ Bh, const __nv_bfloat16* __restrict__ Bl,
    const float* __restrict__ bias, const float* __restrict__ res,
    float* __restrict__ C, __nv_bfloat16* __restrict__ Oh, __nv_bfloat16* __restrict__ Ol,
    int M, int N, int K)
{
    extern __shared__ char smem[];
    constexpr int RS = 64;
    constexpr int BUF = 128 * RS;
    constexpr int STAGE = 4 * BUF;
    uint32_t sb = smem_u32(smem);
    int tid = threadIdx.x, wid = tid >> 5, lane = tid & 31;
    int wm = wid >> 2, wn = wid & 3;
    int n0 = blockIdx.x * 128, m0 = blockIdx.y * 128;

    const char* pAh = (const char*)(Ah + (size_t)m0 * K);
    const char* pAl = (const char*)(Al + (size_t)m0 * K);
    const char* pBh = (const char*)(Bh + (size_t)n0 * K);
    const char* pBl = (const char*)(Bl + (size_t)n0 * K);
    int nCh = K >> 5;

    auto load_chunk = [&](int s, int kc) {
        uint32_t base = sb + s * STAGE;
        size_t kb = (size_t)kc * 64;
        #pragma unroll
        for (int idx = tid; idx < 512; idx += 256) {
            int r = idx >> 2, g = idx & 3;
            uint32_t d = base + r * RS + SWIZ(r, g) * 16;
            size_t go = (size_t)r * (K * 2) + kb + g * 16;
            cp16(d,       pAh + go, 16);
            cp16(d + BUF, pAl + go, 16);
        }
        #pragma unroll
        for (int idx = tid; idx < 512; idx += 256) {
            int r = idx >> 2, g = idx & 3;
            bool ok = (n0 + r) < N;
            size_t go = (size_t)(ok ? r : 0) * (K * 2) + kb + g * 16;
            uint32_t d = base + r * RS + SWIZ(r, g) * 16;
            cp16(d + 2 * BUF, pBh + go, ok ? 16u : 0u);
            cp16(d + 3 * BUF, pBl + go, ok ? 16u : 0u);
        }
        cp_commit();
    };

    float acc[4][4][4];
    #pragma unroll
    for (int i = 0; i < 4; i++)
        #pragma unroll
        for (int j = 0; j < 4; j++)
            #pragma unroll
            for (int k = 0; k < 4; k++) acc[i][j][k] = 0.f;

    int a_row = lane & 15;
    int a_ch  = lane >> 4;
    int b_row = (lane & 7) + ((lane >> 4) << 3);
    int b_ch  = (lane >> 3) & 1;

    load_chunk(0, 0);
    for (int i = 0; i < nCh; i++) {
        if (i + 1 < nCh) { load_chunk((i + 1) & 1, i + 1); cp_wait_one(); }
        else             { cp_wait_all(); }
        __syncthreads();
        uint32_t base = sb + (i & 1) * STAGE;
        #pragma unroll
        for (int kk = 0; kk < 2; kk++) {
            int ch0 = kk * 2;
            uint32_t bh[4][2], bl[4][2];
            #pragma unroll
            for (int half = 0; half < 2; half++) {
                int r = wn * 32 + half * 16 + b_row;
                uint32_t bd = base + 2 * BUF + r * RS + SWIZ(r, ch0 + b_ch) * 16;
                uint32_t t[4];
                LDSM4(t, bd);
                bh[2*half][0] = t[0]; bh[2*half][1] = t[1];
                bh[2*half+1][0] = t[2]; bh[2*half+1][1] = t[3];
                LDSM4(t, bd + BUF);
                bl[2*half][0] = t[0]; bl[2*half][1] = t[1];
                bl[2*half+1][0] = t[2]; bl[2*half+1][1] = t[3];
            }
            #pragma unroll
            for (int mt = 0; mt < 4; mt++) {
                int r = wm * 64 + mt * 16 + a_row;
                uint32_t ad = base + r * RS + SWIZ(r, ch0 + a_ch) * 16;
                uint32_t ah[4], al[4];
                LDSM4(ah, ad);
                LDSM4(al, ad + BUF);
                #pragma unroll
                for (int nt = 0; nt < 4; nt++) {
                    MMA_BF16(acc[mt][nt], ah, bh[nt]);
                    MMA_BF16(acc[mt][nt], ah, bl[nt]);
                    MMA_BF16(acc[mt][nt], al, bh[nt]);
                }
            }
        }
        __syncthreads();
    }

    int lr = lane >> 2, lc = (lane & 3) << 1;
    int rbase = m0 + wm * 64, cbase = n0 + wn * 32;
    #pragma unroll
    for (int mt = 0; mt < 4; mt++) {
        #pragma unroll
        for (int nt = 0; nt < 4; nt++) {
            int c = cbase + nt * 8 + lc;
            float b0 = 0.f, b1 = 0.f;
            if (EPI != 3) { b0 = bias[c]; b1 = bias[c + 1]; }
            #pragma unroll
            for (int half = 0; half < 2; half++) {
                int row = rbase + mt * 16 + lr + half * 8;
                size_t off = (size_t)row * N + c;
                float v0 = acc[mt][nt][2 * half]     + b0;
                float v1 = acc[mt][nt][2 * half + 1] + b1;
                if (EPI == 1) {
                    float2 rr = *(const float2*)(res + off);
                    v0 += rr.x; v1 += rr.y;
                }
                if (EPI == 2) {
                    v0 = gelu_f(v0); v1 = gelu_f(v1);
                    split_store(v0, Oh + off,     Ol + off);
                    split_store(v1, Oh + off + 1, Ol + off + 1);
                } else if (EPI == 3) {
                    if (c < N)     C[off]     = acc[mt][nt][2 * half];
                    if (c + 1 < N) C[off + 1] = acc[mt][nt][2 * half + 1];
                } else {
                    *(float2*)(C + off) = make_float2(v0, v1);
                }
            }
        }
    }
}

// ---------------- embedding ---------------------------------------------------
__global__ void __launch_bounds__(256) embed_kernel(
    const int* __restrict__ ids, const float* __restrict__ tok,
    const float* __restrict__ pos, float* __restrict__ x)
{
    int i = blockIdx.x * 256 + threadIdx.x;
    int d = i % D_, t = i / D_, s = t & (S_ - 1);
    x[i] = tok[(size_t)ids[t] * D_ + d] + pos[(size_t)s * D_ + d];
}

// ---------------- layernorm -> bf16 hi/lo -------------------------------------
__global__ void __launch_bounds__(256) ln_split_kernel(
    const float* __restrict__ x, const float* __restrict__ g,
    const float* __restrict__ b, __nv_bfloat16* __restrict__ oh,
    __nv_bfloat16* __restrict__ ol)
{
    int row = blockIdx.x, tid = threadIdx.x;
    const float* xr = x + (size_t)row * D_;
    float v0 = xr[tid], v1 = xr[tid + 256], v2 = xr[tid + 512];
    __shared__ float red[8];
    __shared__ float s_stat;
    float s = v0 + v1 + v2;
    #pragma unroll
    for (int o = 16; o; o >>= 1) s += __shfl_xor_sync(0xffffffffu, s, o);
    if ((tid & 31) == 0) red[tid >> 5] = s;
    __syncthreads();
    if (tid == 0) {
        float t = 0.f;
        #pragma unroll
        for (int i = 0; i < 8; i++) t += red[i];
        s_stat = t * (1.0f / D_);
    }
    __syncthreads();
    float mean = s_stat;
    __syncthreads();
    float d0 = v0 - mean, d1 = v1 - mean, d2 = v2 - mean;
    float s2 = d0*d0 + d1*d1 + d2*d2;
    #pragma unroll
    for (int o = 16; o; o >>= 1) s2 += __shfl_xor_sync(0xffffffffu, s2, o);
    if ((tid & 31) == 0) red[tid >> 5] = s2;
    __syncthreads();
    if (tid == 0) {
        float t = 0.f;
        #pragma unroll
        for (int i = 0; i < 8; i++) t += red[i];
        s_stat = rsqrtf(t * (1.0f / D_) + 1e-5f);
    }
    __syncthreads();
    float inv = s_stat;
    size_t base = (size_t)row * D_;
    split_store(g[tid]     * (d0*inv) + b[tid],     oh + base + tid,       ol + base + tid);
    split_store(g[tid+256] * (d1*inv) + b[tid+256], oh + base + tid + 256, ol + base + tid + 256);
    split_store(g[tid+512] * (d2*inv) + b[tid+512], oh + base + tid + 512, ol + base + tid + 512);
}

// ---------------- fused flash attention (tensor-core, online softmax) ----------
// CTA = (qt, bh): 64 q rows, 4 warps x 16 rows. kt loop over causal 64-wide tiles.
// S = Q K^T via split-bf16 mma; softmax in fragment regs (quad shuffles);
// P repacked C-frag -> A-frag (hi/lo); O += P V via split mma with V^T in smem.
#define FROW 72   // padded row: 72 bf16 = 144 bytes (conflict-free ldmatrix)
__global__ void __launch_bounds__(128) flash_kernel(
    const float* __restrict__ qkv, __nv_bfloat16* __restrict__ oh,
    __nv_bfloat16* __restrict__ ol)
{
    extern __shared__ char fsm[];
    __nv_bfloat16* sQh = (__nv_bfloat16*)fsm;       // [64][FROW]
    __nv_bfloat16* sQl = sQh + 64 * FROW;
    __nv_bfloat16* sKh = sQl + 64 * FROW;
    __nv_bfloat16* sKl = sKh + 64 * FROW;
    __nv_bfloat16* sVh = sKl + 64 * FROW;           // V^T: [d][k]
    __nv_bfloat16* sVl = sVh + 64 * FROW;

    int qt = blockIdx.x, bh = blockIdx.y;
    int b = bh / H_, h = bh - b * H_;
    int tid = threadIdx.x, warp = tid >> 5, lane = tid & 31;

    const float* Qg = qkv + ((size_t)(b * S_ + qt * 64)) * (3 * D_) + h * HD_;
    const float* Kg = qkv + (size_t)b * S_ * (3 * D_) + D_ + h * HD_;
    const float* Vg = qkv + (size_t)b * S_ * (3 * D_) + 2 * D_ + h * HD_;

    // load Q tile (64 x 64), split hi/lo
    for (int idx = tid; idx < 1024; idx += 128) {
        int r = idx >> 4, d4 = (idx & 15) << 2;
        float4 v = *(const float4*)(Qg + (size_t)r * (3 * D_) + d4);
        float vv[4] = {v.x, v.y, v.z, v.w};
        #pragma unroll
        for (int j = 0; j < 4; j++)
            split_smem(vv[j], sQh + r * FROW + d4 + j, sQl + r * FROW + d4 + j);
    }

    int a_row = lane & 15, a_ch = lane >> 4;
    int b_row = (lane & 7) + ((lane >> 4) << 3);
    int b_ch = (lane >> 3) & 1;
    uint32_t uQh = smem_u32(sQh), uQl = smem_u32(sQl);
    uint32_t uKh = smem_u32(sKh), uKl = smem_u32(sKl);
    uint32_t uVh = smem_u32(sVh), uVl = smem_u32(sVl);

    float oacc[8][4];
    #pragma unroll
    for (int i = 0; i < 8; i++)
        #pragma unroll
        for (int j = 0; j < 4; j++) oacc[i][j] = 0.f;
    float m0 = -1e30f, m1 = -1e30f, l0 = 0.f, l1 = 0.f;

    for (int kt = 0; kt <= qt; kt++) {
        __syncthreads();                 // protect K/V smem from previous PV reads
        for (int idx = tid; idx < 1024; idx += 128) {
            int r = idx >> 4, d4 = (idx & 15) << 2;
            float4 kv = *(const float4*)(Kg + (size_t)(kt * 64 + r) * (3 * D_) + d4);
            float4 vv = *(const float4*)(Vg + (size_t)(kt * 64 + r) * (3 * D_) + d4);
            float ka[4] = {kv.x, kv.y, kv.z, kv.w};
            float va[4] = {vv.x, vv.y, vv.z, vv.w};
            #pragma unroll
            for (int j = 0; j < 4; j++) {
                split_smem(ka[j], sKh + r * FROW + d4 + j, sKl + r * FROW + d4 + j);
                split_smem(va[j], sVh + (d4 + j) * FROW + r, sVl + (d4 + j) * FROW + r); // V^T
            }
        }
        __syncthreads();

        // ---- S = Q K^T (16 rows x 64 cols per warp) ----
        float sacc[8][4];
        #pragma unroll
        for (int i = 0; i < 8; i++)
            #pragma unroll
            for (int j = 0; j < 4; j++) sacc[i][j] = 0.f;
        #pragma unroll
        for (int s16 = 0; s16 < 4; s16++) {
            uint32_t aoff = (uint32_t)((16 * warp + a_row) * (FROW * 2) + s16 * 32 + a_ch * 16);
            uint32_t qh_[4], ql_[4];
            LDSM4(qh_, uQh + aoff);
            LDSM4(ql_, uQl + aoff);
            #pragma unroll
            for (int g = 0; g < 4; g++) {
                uint32_t boff = (uint32_t)((16 * g + b_row) * (FROW * 2) + s16 * 32 + b_ch * 16);
                uint32_t th_[4], tl_[4];
                LDSM4(th_, uKh + boff);
                LDSM4(tl_, uKl + boff);
                uint32_t bh0[2] = {th_[0], th_[1]}, bh1[2] = {th_[2], th_[3]};
                uint32_t bl0[2] = {tl_[0], tl_[1]}, bl1[2] = {tl_[2], tl_[3]};
                MMA_BF16(sacc[2*g],   qh_, bh0); MMA_BF16(sacc[2*g],   qh_, bl0); MMA_BF16(sacc[2*g],   ql_, bh0);
                MMA_BF16(sacc[2*g+1], qh_, bh1); MMA_BF16(sacc[2*g+1], qh_, bl1); MMA_BF16(sacc[2*g+1], ql_, bh1);
            }
        }
        #pragma unroll
        for (int i = 0; i < 8; i++)
            #pragma unroll
            for (int j = 0; j < 4; j++) sacc[i][j] *= 0.125f;   // 1/sqrt(64)

        // causal mask only on the diagonal tile
        if (kt == qt) {
            int r0 = 16 * warp + (lane >> 2);
            #pragma unroll
            for (int nt = 0; nt < 8; nt++)
                #pragma unroll
                for (int j = 0; j < 4; j++) {
                    int col = nt * 8 + 2 * (lane & 3) + (j & 1);
                    int row = r0 + ((j >> 1) << 3);
                    if (col > row) sacc[nt][j] = -1e30f;
                }
        }

        // ---- online softmax (rows r0 = 16w + lane>>2, r1 = r0+8) ----
        float mx0 = -1e30f, mx1 = -1e30f;
        #pragma unroll
        for (int nt = 0; nt < 8; nt++) {
            mx0 = fmaxf(mx0, fmaxf(sacc[nt][0], sacc[nt][1]));
            mx1 = fmaxf(mx1, fmaxf(sacc[nt][2], sacc[nt][3]));
        }
        mx0 = fmaxf(mx0, __shfl_xor_sync(0xffffffffu, mx0, 1));
        mx0 = fmaxf(mx0, __shfl_xor_sync(0xffffffffu, mx0, 2));
        mx1 = fmaxf(mx1, __shfl_xor_sync(0xffffffffu, mx1, 1));
        mx1 = fmaxf(mx1, __shfl_xor_sync(0xffffffffu, mx1, 2));
        float m0n = fmaxf(m0, mx0), m1n = fmaxf(m1, mx1);
        float sc0 = __expf(m0 - m0n), sc1 = __expf(m1 - m1n);
        float sum0 = 0.f, sum1 = 0.f;
        #pragma unroll
        for (int nt = 0; nt < 8; nt++) {
            sacc[nt][0] = __expf(sacc[nt][0] - m0n); sum0 += sacc[nt][0];
            sacc[nt][1] = __expf(sacc[nt][1] - m0n); sum0 += sacc[nt][1];
            sacc[nt][2] = __expf(sacc[nt][2] - m1n); sum1 += sacc[nt][2];
            sacc[nt][3] = __expf(sacc[nt][3] - m1n); sum1 += sacc[nt][3];
        }
        sum0 += __shfl_xor_sync(0xffffffffu, sum0, 1);
        sum0 += __shfl_xor_sync(0xffffffffu, sum0, 2);
        sum1 += __shfl_xor_sync(0xffffffffu, sum1, 1);
        sum1 += __shfl_xor_sync(0xffffffffu, sum1, 2);
        l0 = l0 * sc0 + sum0;  l1 = l1 * sc1 + sum1;
        m0 = m0n;  m1 = m1n;
        #pragma unroll
        for (int nt = 0; nt < 8; nt++) {
            oacc[nt][0] *= sc0; oacc[nt][1] *= sc0;
            oacc[nt][2] *= sc1; oacc[nt][3] *= sc1;
        }

        // ---- O += P V  (P C-frag -> A-frag repack, hi/lo split) ----
        #pragma unroll
        for (int s16 = 0; s16 < 4; s16++) {
            uint32_t pah[4], pal[4];
            split_pack2(sacc[2*s16][0],   sacc[2*s16][1],   pah[0], pal[0]);
            split_pack2(sacc[2*s16][2],   sacc[2*s16][3],   pah[1], pal[1]);
            split_pack2(sacc[2*s16+1][0], sacc[2*s16+1][1], pah[2], pal[2]);
            split_pack2(sacc[2*s16+1][2], sacc[2*s16+1][3], pah[3], pal[3]);
            #pragma unroll
            for (int g = 0; g < 4; g++) {
                uint32_t boff = (uint32_t)((16 * g + b_row) * (FROW * 2) + s16 * 32 + b_ch * 16);
                uint32_t th_[4], tl_[4];
                LDSM4(th_, uVh + boff);
                LDSM4(tl_, uVl + boff);
                uint32_t vh0[2] = {th_[0], th_[1]}, vh1[2] = {th_[2], th_[3]};
                uint32_t vl0[2] = {tl_[0], tl_[1]}, vl1[2] = {tl_[2], tl_[3]};
                MMA_BF16(oacc[2*g],   pah, vh0); MMA_BF16(oacc[2*g],   pah, vl0); MMA_BF16(oacc[2*g],   pal, vh0);
                MMA_BF16(oacc[2*g+1], pah, vh1); MMA_BF16(oacc[2*g+1], pah, vl1); MMA_BF16(oacc[2*g+1], pal, vh1);
            }
        }
    }

    // ---- finalize: divide by l, split-store O hi/lo ----
    float i0 = 1.f / l0, i1 = 1.f / l1;
    int r0 = qt * 64 + 16 * warp + (lane >> 2);
    #pragma unroll
    for (int nt = 0; nt < 8; nt++) {
        int c = nt * 8 + ((lane & 3) << 1);
        #pragma unroll
        for (int half = 0; half < 2; half++) {
            int row = r0 + half * 8;
            size_t off = (size_t)(b * S_ + row) * D_ + h * HD_ + c;
            float v0 = oacc[nt][2 * half]     * (half ? i1 : i0);
            float v1 = oacc[nt][2 * half + 1] * (half ? i1 : i0);
            uint32_t hw, lw;
            split_pack2(v0, v1, hw, lw);
            *(uint32_t*)(oh + off) = hw;
            *(uint32_t*)(ol + off) = lw;
        }
    }
}

// ---------------- host orchestration ------------------------------------------
extern "C" void kernel_launch(void* const* d_in, const int* in_sizes, int n_in,
                              void* d_out, int out_size)
{
    const int*   ids  = (const int*)d_in[0];
    const float* tok  = (const float*)d_in[1];
    const float* pos  = (const float*)d_in[2];
    const float* ln1g = (const float*)d_in[3];
    const float* ln1b = (const float*)d_in[4];
    const float* qkvw = (const float*)d_in[5];
    const float* qkvb = (const float*)d_in[6];
    const float* outw = (const float*)d_in[7];
    const float* outb = (const float*)d_in[8];
    const float* ln2g = (const float*)d_in[9];
    const float* ln2b = (const float*)d_in[10];
    const float* f1w  = (const float*)d_in[11];
    const float* f1b  = (const float*)d_in[12];
    const float* f2w  = (const float*)d_in[13];
    const float* f2b  = (const float*)d_in[14];
    const float* lnfg = (const float*)d_in[15];
    const float* lnfb = (const float*)d_in[16];
    float* logits = (float*)d_out;

    float *x, *qkv;
    cudaGetSymbolAddress((void**)&x,   g_x);
    cudaGetSymbolAddress((void**)&qkv, g_qkv);
    __nv_bfloat16 *qh, *ql, *ow_h, *ow_l, *f1h, *f1l, *f2h, *f2l, *th, *tl;
    __nv_bfloat16 *hh, *hl, *oh, *ol, *fh, *fl;
    cudaGetSymbolAddress((void**)&qh,   g_qkvw_h);  cudaGetSymbolAddress((void**)&ql,   g_qkvw_l);
    cudaGetSymbolAddress((void**)&ow_h, g_outw_h);  cudaGetSymbolAddress((void**)&ow_l, g_outw_l);
    cudaGetSymbolAddress((void**)&f1h,  g_fc1w_h);  cudaGetSymbolAddress((void**)&f1l,  g_fc1w_l);
    cudaGetSymbolAddress((void**)&f2h,  g_fc2w_h);  cudaGetSymbolAddress((void**)&f2l,  g_fc2w_l);
    cudaGetSymbolAddress((void**)&th,   g_tok_h);   cudaGetSymbolAddress((void**)&tl,   g_tok_l);
    cudaGetSymbolAddress((void**)&hh,   g_hh);      cudaGetSymbolAddress((void**)&hl,   g_hl);
    cudaGetSymbolAddress((void**)&oh,   g_oh);      cudaGetSymbolAddress((void**)&ol,   g_ol);
    cudaGetSymbolAddress((void**)&fh,   g_fh);      cudaGetSymbolAddress((void**)&fl,   g_fl);

    constexpr int SMEM = 2 * 4 * 128 * 64;           // GEMM: 64KB double-buffered
    constexpr int FSMEM = 6 * 64 * FROW * 2;         // flash: 55296 B
    cudaFuncSetAttribute(gemm_mma<0>, cudaFuncAttributeMaxDynamicSharedMemorySize, SMEM);
    cudaFuncSetAttribute(gemm_mma<1>, cudaFuncAttributeMaxDynamicSharedMemorySize, SMEM);
    cudaFuncSetAttribute(gemm_mma<2>, cudaFuncAttributeMaxDynamicSharedMemorySize, SMEM);
    cudaFuncSetAttribute(gemm_mma<3>, cudaFuncAttributeMaxDynamicSharedMemorySize, SMEM);
    cudaFuncSetAttribute(flash_kernel, cudaFuncAttributeMaxDynamicSharedMemorySize, FSMEM);

    // one-time-per-launch weight conversion (transpose to [N,K] hi/lo)
    wconv_kernel<<<dim3(3*D_/32, D_/32, L_), 256>>>(qkvw, qh, ql, D_, 3*D_);
    wconv_kernel<<<dim3(D_/32,   D_/32, L_), 256>>>(outw, ow_h, ow_l, D_, D_);
    wconv_kernel<<<dim3(F_/32,   D_/32, L_), 256>>>(f1w, f1h, f1l, D_, F_);
    wconv_kernel<<<dim3(D_/32,   F_/32, L_), 256>>>(f2w, f2h, f2l, F_, D_);
    tconv_kernel<<<(int)(((size_t)V_*D_)/256), 256>>>(tok, th, tl);

    embed_kernel<<<(T_ * D_) / 256, 256>>>(ids, tok, pos, x);

    for (int l = 0; l < L_; l++) {
        ln_split_kernel<<<T_, 256>>>(x, ln1g + l * D_, ln1b + l * D_, hh, hl);
        gemm_mma<0><<<dim3(3*D_/128, T_/128), 256, SMEM>>>(
            hh, hl, qh + (size_t)l*3*D_*D_, ql + (size_t)l*3*D_*D_,
            qkvb + (size_t)l*3*D_, nullptr, qkv, nullptr, nullptr, T_, 3*D_, D_);

        flash_kernel<<<dim3(16, B_ * H_), 128, FSMEM>>>(qkv, oh, ol);

        gemm_mma<1><<<dim3(D_/128, T_/128), 256, SMEM>>>(
            oh, ol, ow_h + (size_t)l*D_*D_, ow_l + (size_t)l*D_*D_,
            outb + (size_t)l*D_, x, x, nullptr, nullptr, T_, D_, D_);

        ln_split_kernel<<<T_, 256>>>(x, ln2g + l * D_, ln2b + l * D_, hh, hl);
        gemm_mma<2><<<dim3(F_/128, T_/128), 256, SMEM>>>(
            hh, hl, f1h + (size_t)l*F_*D_, f1l + (size_t)l*F_*D_,
            f1b + (size_t)l*F_, nullptr, nullptr, fh, fl, T_, F_, D_);

        gemm_mma<1><<<dim3(D_/128, T_/128), 256, SMEM>>>(
            fh, fl, f2h + (size_t)l*D_*F_, f2l + (size_t)l*D_*F_,
            f2b + (size_t)l*D_, x, x, nullptr, nullptr, T_, D_, F_);
    }

    ln_split_kernel<<<T_, 256>>>(x, lnfg, lnfb, hh, hl);
    gemm_mma<3><<<dim3((V_ + 127)/128, T_/128), 256, SMEM>>>(
        hh, hl, th, tl, nullptr, nullptr, logits, nullptr, nullptr, T_, V_, D_);
}